// round 4
// baseline (speedup 1.0000x reference)
#include <cuda_runtime.h>
#include <math.h>

// Problem constants
#define NB 2
#define NS 2048
#define NE 1024
#define NH 16
#define ND 64
#define NM (NB*NS)   // 4096 rows

// ---------------- scratch (static device globals; no allocation) -------------
__device__ float g_q[NB*NH*NS*ND];    // [B,H,S,D] roped, pre-scaled by 1/sqrt(D)
__device__ float g_k[NB*NH*NS*ND];    // [B,H,S,D] roped
__device__ float g_v[NB*NH*NS*ND];    // [B,H,S,D]
__device__ float g_att[NB*NS*NE];     // [B,S,H,D] == [B,S,E]
__device__ float g_cos[(ND/2)*NS];    // [d2][s]
__device__ float g_sin[(ND/2)*NS];

// Build RoPE tables. Bit-identical to: invf = float(10000^(-2*d2/D));
// ang = float(s) * invf (fp32); sincosf(ang).
__global__ void init_tabs_kernel() {
    int idx = blockIdx.x * 256 + threadIdx.x;     // 0 .. 32*2048-1
    int d2 = idx >> 11;
    int s  = idx & (NS-1);
    double ex = (double)(2*d2) / (double)ND;
    float invf = (float)exp2(-ex * 13.287712379549449); // 10000^(-2*d2/D)
    float ang = (float)s * invf;
    float sn, cs;
    sincosf(ang, &sn, &cs);
    g_cos[idx] = cs;
    g_sin[idx] = sn;
}

// ---------------- tf32 helpers ------------------------------------------------
__device__ __forceinline__ unsigned f2tf(float x) {
    unsigned u;
    asm("cvt.rna.tf32.f32 %0, %1;" : "=r"(u) : "f"(x));
    return u;
}

__device__ __forceinline__ void mma_tf32(float c[4], const unsigned a[4], const unsigned b[2]) {
    asm volatile(
        "mma.sync.aligned.m16n8k8.row.col.f32.tf32.tf32.f32 "
        "{%0,%1,%2,%3}, {%4,%5,%6,%7}, {%8,%9}, {%0,%1,%2,%3};"
        : "+f"(c[0]), "+f"(c[1]), "+f"(c[2]), "+f"(c[3])
        : "r"(a[0]), "r"(a[1]), "r"(a[2]), "r"(a[3]),
          "r"(b[0]), "r"(b[1]));
}

// ---------------- GEMM: C[m,n] = sum_k A[m,k]*Wt[n,k] + bias[n] --------------
// BM=128, BN=128, BK=32. 256 threads = 8 warps (2 m-warps x 4 n-warps).
// 2-stage smem pipeline: LDG(next) -> mma(cur) -> STS(next) -> 1 sync.
#define ASTR 36             // 36 % 32 == 4 -> conflict-free fragment loads
#define GA_ST (128*ASTR)    // u32 per matrix per stage
#define GEMM_SMEM (4*GA_ST*4)   // bytes: 2 matrices x 2 stages

template<int MODE>
__global__ __launch_bounds__(256) void gemm_tc(
    const float* __restrict__ Ain, const float* __restrict__ Wt,
    const float* __restrict__ bias, float* __restrict__ Cout)
{
    const float* A = (MODE == 0) ? (const float*)g_att : Ain;
    extern __shared__ unsigned sm[];
    unsigned* AsB = sm;              // [2][GA_ST]
    unsigned* BsB = sm + 2*GA_ST;    // [2][GA_ST]

    int tid  = threadIdx.x;
    int lane = tid & 31, wid = tid >> 5;
    int wm = wid & 1, wn = wid >> 1;
    int g = lane >> 2, tg = lane & 3;
    int m0 = blockIdx.y * 128;
    int n0 = blockIdx.x * 128;

    float c[4][4][4];
    #pragma unroll
    for (int mt = 0; mt < 4; mt++)
        #pragma unroll
        for (int nt = 0; nt < 4; nt++)
            #pragma unroll
            for (int j = 0; j < 4; j++) c[mt][nt][j] = 0.f;

    // staging registers + fixed per-thread load coordinates
    float4 ra[4], rb[4];
    int rowi[4], kci[4];
    #pragma unroll
    for (int i = 0; i < 4; i++) {
        int f4 = tid + i*256;
        rowi[i] = f4 >> 3;          // 0..127
        kci[i]  = (f4 & 7) << 2;    // 0..28
    }

    auto ldg = [&](int kk) {
        #pragma unroll
        for (int i = 0; i < 4; i++) {
            ra[i] = *(const float4*)(A  + (size_t)(m0+rowi[i])*NE + kk + kci[i]);
            rb[i] = *(const float4*)(Wt + (size_t)(n0+rowi[i])*NE + kk + kci[i]);
        }
    };
    auto sts = [&](int st) {
        unsigned* As = AsB + st*GA_ST;
        unsigned* Bs = BsB + st*GA_ST;
        #pragma unroll
        for (int i = 0; i < 4; i++) {
            *(uint4*)&As[rowi[i]*ASTR + kci[i]] =
                make_uint4(f2tf(ra[i].x), f2tf(ra[i].y), f2tf(ra[i].z), f2tf(ra[i].w));
            *(uint4*)&Bs[rowi[i]*ASTR + kci[i]] =
                make_uint4(f2tf(rb[i].x), f2tf(rb[i].y), f2tf(rb[i].z), f2tf(rb[i].w));
        }
    };

    ldg(0); sts(0); __syncthreads();
    int cur = 0;

    for (int kk = 0; kk < NE; kk += 32) {
        bool more = (kk + 32) < NE;
        if (more) ldg(kk + 32);

        const unsigned* As = AsB + cur*GA_ST;
        const unsigned* Bs = BsB + cur*GA_ST;
        #pragma unroll
        for (int ks = 0; ks < 4; ks++) {
            unsigned a[4][4], b[4][2];
            int cidx = ks*8 + tg;
            #pragma unroll
            for (int mt = 0; mt < 4; mt++) {
                int r = wm*64 + mt*16 + g;
                a[mt][0] = As[r*ASTR + cidx];
                a[mt][1] = As[(r+8)*ASTR + cidx];
                a[mt][2] = As[r*ASTR + cidx + 4];
                a[mt][3] = As[(r+8)*ASTR + cidx + 4];
            }
            #pragma unroll
            for (int nt = 0; nt < 4; nt++) {
                int n = wn*32 + nt*8 + g;
                b[nt][0] = Bs[n*ASTR + cidx];
                b[nt][1] = Bs[n*ASTR + cidx + 4];
            }
            #pragma unroll
            for (int mt = 0; mt < 4; mt++)
                #pragma unroll
                for (int nt = 0; nt < 4; nt++)
                    mma_tf32(c[mt][nt], a[mt], b[nt]);
        }

        if (more) sts(cur ^ 1);
        __syncthreads();
        cur ^= 1;
    }

    // Epilogue: per (mt,nt) tile the thread holds (r0,col),(r0,col+1),(r0+8,col),(r0+8,col+1)
    // with col even -> perfect RoPE even/odd pairing.
    #pragma unroll
    for (int mt = 0; mt < 4; mt++) {
        int r0 = m0 + wm*64 + mt*16 + g;
        #pragma unroll
        for (int nt = 0; nt < 4; nt++) {
            int col = n0 + wn*32 + nt*8 + 2*tg;
            float b0 = bias[col], b1 = bias[col+1];
            float v00 = c[mt][nt][0] + b0, v01 = c[mt][nt][1] + b1;  // row r0
            float v10 = c[mt][nt][2] + b0, v11 = c[mt][nt][3] + b1;  // row r0+8
            if (MODE == 0) {
                *(float2*)(Cout + (size_t)r0*NE + col)     = make_float2(v00, v01);
                *(float2*)(Cout + (size_t)(r0+8)*NE + col) = make_float2(v10, v11);
            } else {
                float* dstbase = (MODE == 1) ? g_q : (MODE == 2) ? g_k : g_v;
                int h = col >> 6;
                int d = col & 63;               // even
                #pragma unroll
                for (int rr = 0; rr < 2; rr++) {
                    int r = r0 + rr*8;
                    int b = r >> 11;            // / NS
                    int s = r & (NS-1);
                    float ve = rr ? v10 : v00;
                    float vo = rr ? v11 : v01;
                    float oe, oo;
                    if (MODE == 3) {
                        oe = ve; oo = vo;
                    } else {
                        int ti = (d >> 1)*NS + s;
                        float cs = g_cos[ti];
                        float sn = g_sin[ti];
                        oe = ve*cs - vo*sn;
                        oo = vo*cs + ve*sn;
                        if (MODE == 1) { oe *= 0.125f; oo *= 0.125f; }
                    }
                    *(float2*)(dstbase + ((size_t)((b*NH + h)*NS + s))*ND + d)
                        = make_float2(oe, oo);
                }
            }
        }
    }
}

// ---------------- Flash attention, tf32 tensor cores, pipelined --------------
// CTA: 128 q-rows, 8 warps (16 q-rows each). 64-key tiles, 2-stage smem pipeline.
#define KSTR 68   // 68 % 32 == 4 : conflict-free for (g, tg) pattern
#define VSTR 72   // 72 % 32 == 8 : conflict-free for (tg row, g col) pattern
#define KST (64*KSTR)
#define VST (64*VSTR)
#define ATTN_SMEM ((2*KST + 2*VST)*4)

__global__ __launch_bounds__(256) void attn_tc()
{
    extern __shared__ unsigned sm[];
    unsigned* KsB = sm;            // [2][KST]
    unsigned* VsB = sm + 2*KST;    // [2][VST]

    int tid  = threadIdx.x;
    int lane = tid & 31, wid = tid >> 5;
    int g = lane >> 2, tg = lane & 3;
    int bh = blockIdx.y;
    int q0 = blockIdx.x * 128;

    const float* qp = g_q + (size_t)bh * NS * ND;
    const float* kp = g_k + (size_t)bh * NS * ND;
    const float* vp = g_v + (size_t)bh * NS * ND;

    // Q fragments for this warp's 16 rows (rows r0, r0+8), all of d=64
    int r0 = q0 + wid*16 + g;
    unsigned qa[8][4];
    #pragma unroll
    for (int ks = 0; ks < 8; ks++) {
        int cc = ks*8 + tg;
        qa[ks][0] = f2tf(qp[(size_t)r0*ND + cc]);
        qa[ks][1] = f2tf(qp[(size_t)(r0+8)*ND + cc]);
        qa[ks][2] = f2tf(qp[(size_t)r0*ND + cc + 4]);
        qa[ks][3] = f2tf(qp[(size_t)(r0+8)*ND + cc + 4]);
    }

    float o[8][4];
    #pragma unroll
    for (int nt = 0; nt < 8; nt++)
        #pragma unroll
        for (int j = 0; j < 4; j++) o[nt][j] = 0.f;
    float m0r = -INFINITY, m1r = -INFINITY, l0 = 0.f, l1 = 0.f;

    int srcA = (lane & ~3) | (tg >> 1);
    int srcB = srcA + 2;
    bool oddl = (tg & 1);

    // staging registers + fixed load coordinates
    float4 rk[4], rv[4];
    int rri[4], cci[4];
    #pragma unroll
    for (int i = 0; i < 4; i++) {
        int f4 = tid + i*256;
        rri[i] = f4 >> 4;            // 0..63
        cci[i] = (f4 & 15) << 2;     // 0..60
    }
    auto ldg = [&](int kt) {
        #pragma unroll
        for (int i = 0; i < 4; i++) {
            rk[i] = *(const float4*)(kp + (size_t)(kt+rri[i])*ND + cci[i]);
            rv[i] = *(const float4*)(vp + (size_t)(kt+rri[i])*ND + cci[i]);
        }
    };
    auto sts = [&](int st) {
        unsigned* Ks = KsB + st*KST;
        unsigned* Vs = VsB + st*VST;
        #pragma unroll
        for (int i = 0; i < 4; i++) {
            *(uint4*)&Ks[rri[i]*KSTR + cci[i]] =
                make_uint4(f2tf(rk[i].x), f2tf(rk[i].y), f2tf(rk[i].z), f2tf(rk[i].w));
            *(uint4*)&Vs[rri[i]*VSTR + cci[i]] =
                make_uint4(f2tf(rv[i].x), f2tf(rv[i].y), f2tf(rv[i].z), f2tf(rv[i].w));
        }
    };

    ldg(0); sts(0); __syncthreads();
    int cur = 0;

    for (int kt = 0; kt < NS; kt += 64) {
        bool more = (kt + 64) < NS;
        if (more) ldg(kt + 64);

        const unsigned* Ks = KsB + cur*KST;
        const unsigned* Vs = VsB + cur*VST;

        // ---- S = Q K^T (per warp: 16 q-rows x 64 keys) ----
        float s[8][4];
        #pragma unroll
        for (int nt = 0; nt < 8; nt++)
            #pragma unroll
            for (int j = 0; j < 4; j++) s[nt][j] = 0.f;
        #pragma unroll
        for (int ks = 0; ks < 8; ks++) {
            int cidx = ks*8 + tg;
            #pragma unroll
            for (int nt = 0; nt < 8; nt++) {
                unsigned b[2];
                b[0] = Ks[(nt*8+g)*KSTR + cidx];
                b[1] = Ks[(nt*8+g)*KSTR + cidx + 4];
                mma_tf32(s[nt], qa[ks], b);
            }
        }

        // ---- online softmax (rewrites s[] with tf32 P bits) ----
        float cm0 = -INFINITY, cm1 = -INFINITY;
        #pragma unroll
        for (int nt = 0; nt < 8; nt++) {
            cm0 = fmaxf(cm0, fmaxf(s[nt][0], s[nt][1]));
            cm1 = fmaxf(cm1, fmaxf(s[nt][2], s[nt][3]));
        }
        cm0 = fmaxf(cm0, __shfl_xor_sync(0xffffffffu, cm0, 1));
        cm0 = fmaxf(cm0, __shfl_xor_sync(0xffffffffu, cm0, 2));
        cm1 = fmaxf(cm1, __shfl_xor_sync(0xffffffffu, cm1, 1));
        cm1 = fmaxf(cm1, __shfl_xor_sync(0xffffffffu, cm1, 2));
        float mn0 = fmaxf(m0r, cm0), mn1 = fmaxf(m1r, cm1);
        float corr0 = __expf(m0r - mn0), corr1 = __expf(m1r - mn1);
        m0r = mn0; m1r = mn1;
        l0 *= corr0; l1 *= corr1;

        #pragma unroll
        for (int nt = 0; nt < 8; nt++) {
            float p0 = __expf(s[nt][0] - mn0);
            float p1 = __expf(s[nt][1] - mn0);
            float p2 = __expf(s[nt][2] - mn1);
            float p3 = __expf(s[nt][3] - mn1);
            l0 += p0 + p1;
            l1 += p2 + p3;
            o[nt][0] *= corr0; o[nt][1] *= corr0;
            o[nt][2] *= corr1; o[nt][3] *= corr1;
            s[nt][0] = __uint_as_float(f2tf(p0));
            s[nt][1] = __uint_as_float(f2tf(p1));
            s[nt][2] = __uint_as_float(f2tf(p2));
            s[nt][3] = __uint_as_float(f2tf(p3));
        }

        // ---- O += P V ----  (P C-frag -> A-frag via shuffles)
        #pragma unroll
        for (int ks = 0; ks < 8; ks++) {
            unsigned u0 = __float_as_uint(s[ks][0]);
            unsigned u1 = __float_as_uint(s[ks][1]);
            unsigned u2 = __float_as_uint(s[ks][2]);
            unsigned u3 = __float_as_uint(s[ks][3]);
            unsigned pa[4], e0, e1;
            e0 = __shfl_sync(0xffffffffu, u0, srcA);
            e1 = __shfl_sync(0xffffffffu, u1, srcA);
            pa[0] = oddl ? e1 : e0;
            e0 = __shfl_sync(0xffffffffu, u2, srcA);
            e1 = __shfl_sync(0xffffffffu, u3, srcA);
            pa[1] = oddl ? e1 : e0;
            e0 = __shfl_sync(0xffffffffu, u0, srcB);
            e1 = __shfl_sync(0xffffffffu, u1, srcB);
            pa[2] = oddl ? e1 : e0;
            e0 = __shfl_sync(0xffffffffu, u2, srcB);
            e1 = __shfl_sync(0xffffffffu, u3, srcB);
            pa[3] = oddl ? e1 : e0;
            #pragma unroll
            for (int nt = 0; nt < 8; nt++) {
                unsigned b[2];
                b[0] = Vs[(ks*8+tg)*VSTR + nt*8 + g];
                b[1] = Vs[(ks*8+tg+4)*VSTR + nt*8 + g];
                mma_tf32(o[nt], pa, b);
            }
        }

        if (more) sts(cur ^ 1);
        __syncthreads();
        cur ^= 1;
    }

    // ---- finalize: normalize and write [B,S,H,D] ----
    l0 += __shfl_xor_sync(0xffffffffu, l0, 1);
    l0 += __shfl_xor_sync(0xffffffffu, l0, 2);
    l1 += __shfl_xor_sync(0xffffffffu, l1, 1);
    l1 += __shfl_xor_sync(0xffffffffu, l1, 2);
    float i0 = 1.0f / l0, i1 = 1.0f / l1;

    int b = bh >> 4, h = bh & 15;
    float* dst0 = g_att + (((size_t)(b*NS + r0))  * NH + h) * ND;
    float* dst1 = g_att + (((size_t)(b*NS + r0+8))* NH + h) * ND;
    #pragma unroll
    for (int nt = 0; nt < 8; nt++) {
        int col = nt*8 + 2*tg;
        *(float2*)(dst0 + col) = make_float2(o[nt][0]*i0, o[nt][1]*i0);
        *(float2*)(dst1 + col) = make_float2(o[nt][2]*i1, o[nt][3]*i1);
    }
}

// ------------------------------- launch --------------------------------------
extern "C" void kernel_launch(void* const* d_in, const int* in_sizes, int n_in,
                              void* d_out, int out_size)
{
    const float* query = (const float*)d_in[0];
    const float* key   = (const float*)d_in[1];
    const float* value = (const float*)d_in[2];
    const float* Wq    = (const float*)d_in[3];
    const float* bq    = (const float*)d_in[4];
    const float* Wk    = (const float*)d_in[5];
    const float* bk    = (const float*)d_in[6];
    const float* Wv    = (const float*)d_in[7];
    const float* bv    = (const float*)d_in[8];
    const float* Wo    = (const float*)d_in[9];
    const float* bo    = (const float*)d_in[10];
    float* out = (float*)d_out;

    // raise dynamic smem limits (idempotent host-side calls; not stream ops)
    cudaFuncSetAttribute(gemm_tc<0>, cudaFuncAttributeMaxDynamicSharedMemorySize, GEMM_SMEM);
    cudaFuncSetAttribute(gemm_tc<1>, cudaFuncAttributeMaxDynamicSharedMemorySize, GEMM_SMEM);
    cudaFuncSetAttribute(gemm_tc<2>, cudaFuncAttributeMaxDynamicSharedMemorySize, GEMM_SMEM);
    cudaFuncSetAttribute(gemm_tc<3>, cudaFuncAttributeMaxDynamicSharedMemorySize, GEMM_SMEM);
    cudaFuncSetAttribute(attn_tc,    cudaFuncAttributeMaxDynamicSharedMemorySize, ATTN_SMEM);

    dim3 ggrid(NE/128, NM/128);   // (8, 32)

    init_tabs_kernel<<<(ND/2)*NS/256, 256>>>();
    gemm_tc<1><<<ggrid, 256, GEMM_SMEM>>>(query, Wq, bq, nullptr);
    gemm_tc<2><<<ggrid, 256, GEMM_SMEM>>>(key,   Wk, bk, nullptr);
    gemm_tc<3><<<ggrid, 256, GEMM_SMEM>>>(value, Wv, bv, nullptr);
    attn_tc<<<dim3(NS/128, NB*NH), 256, ATTN_SMEM>>>();
    gemm_tc<0><<<ggrid, 256, GEMM_SMEM>>>(nullptr, Wo, bo, out);
}

// round 5
// speedup vs baseline: 1.0682x; 1.0682x over previous
#include <cuda_runtime.h>
#include <math.h>

// Problem constants
#define NB 2
#define NS 2048
#define NE 1024
#define NH 16
#define ND 64
#define NM (NB*NS)   // 4096 rows

// ---------------- scratch (static device globals; no allocation) -------------
// All matmul operands live in gmem as tf32 bit patterns (stored as unsigned).
__device__ unsigned g_qin[NM*NE];     // tf32(query)
__device__ unsigned g_kin[NM*NE];     // tf32(key)
__device__ unsigned g_vin[NM*NE];     // tf32(value)
__device__ unsigned g_wq[NE*NE];      // tf32(Wq)
__device__ unsigned g_wk[NE*NE];
__device__ unsigned g_wv[NE*NE];
__device__ unsigned g_wo[NE*NE];
__device__ unsigned g_q[NB*NH*NS*ND]; // tf32(roped Q * 0.125), [B,H,S,D]
__device__ unsigned g_k[NB*NH*NS*ND]; // tf32(roped K)
__device__ unsigned g_v[NB*NH*NS*ND]; // tf32(V)
__device__ unsigned g_att[NM*NE];     // tf32(attention out), [B,S,H,D]
__device__ float g_cos[(ND/2)*NS];    // [d2][s]
__device__ float g_sin[(ND/2)*NS];

// ---------------- tf32 helpers ------------------------------------------------
__device__ __forceinline__ unsigned f2tf(float x) {
    unsigned u;
    asm("cvt.rna.tf32.f32 %0, %1;" : "=r"(u) : "f"(x));
    return u;
}

__device__ __forceinline__ void mma_tf32(float c[4], const unsigned a[4], const unsigned b[2]) {
    asm volatile(
        "mma.sync.aligned.m16n8k8.row.col.f32.tf32.tf32.f32 "
        "{%0,%1,%2,%3}, {%4,%5,%6,%7}, {%8,%9}, {%0,%1,%2,%3};"
        : "+f"(c[0]), "+f"(c[1]), "+f"(c[2]), "+f"(c[3])
        : "r"(a[0]), "r"(a[1]), "r"(a[2]), "r"(a[3]),
          "r"(b[0]), "r"(b[1]));
}

__device__ __forceinline__ void cp16(unsigned* smem_dst, const unsigned* gmem_src) {
    unsigned saddr = (unsigned)__cvta_generic_to_shared(smem_dst);
    asm volatile("cp.async.cg.shared.global [%0], [%1], 16;"
                 :: "r"(saddr), "l"(gmem_src) : "memory");
}
#define CP_COMMIT() asm volatile("cp.async.commit_group;" ::: "memory")

// ---------------- init kernels ------------------------------------------------
// RoPE tables, bit-identical to: invf = float(10000^(-2*d2/D));
// ang = float(s)*invf (fp32); sincosf(ang).
__global__ void init_tabs_kernel() {
    int idx = blockIdx.x * 256 + threadIdx.x;     // 0 .. 32*2048-1
    int d2 = idx >> 11;
    int s  = idx & (NS-1);
    double ex = (double)(2*d2) / (double)ND;
    float invf = (float)exp2(-ex * 13.287712379549449);
    float ang = (float)s * invf;
    float sn, cs;
    sincosf(ang, &sn, &cs);
    g_cos[idx] = cs;
    g_sin[idx] = sn;
}

// fp32 -> tf32 bits, bulk convert
__global__ void cvt_kernel(const float4* __restrict__ src, int n4, int which) {
    uint4* dst;
    switch (which) {
        case 0: dst = (uint4*)g_qin; break;
        case 1: dst = (uint4*)g_kin; break;
        case 2: dst = (uint4*)g_vin; break;
        case 3: dst = (uint4*)g_wq;  break;
        case 4: dst = (uint4*)g_wk;  break;
        case 5: dst = (uint4*)g_wv;  break;
        default: dst = (uint4*)g_wo; break;
    }
    int i = blockIdx.x * 256 + threadIdx.x;
    if (i < n4) {
        float4 v = src[i];
        dst[i] = make_uint4(f2tf(v.x), f2tf(v.y), f2tf(v.z), f2tf(v.w));
    }
}

// ---------------- GEMM: C[m,n] = sum_k A[m,k]*Wt[n,k] + bias[n] --------------
// BM=128, BN=128, BK=32. 256 threads = 8 warps (2 m-warps x 4 n-warps).
// 3-stage cp.async pipeline, one __syncthreads per k-tile, 2 CTAs/SM.
// MODE 0: A = g_att, W = g_wo, plain fp32 write to Cout[M,E]
// MODE 1: A = g_qin, W = g_wq, RoPE + 0.125, scatter tf32 to g_q[B,H,S,D]
// MODE 2: A = g_kin, W = g_wk, RoPE,          scatter tf32 to g_k
// MODE 3: A = g_vin, W = g_wv, plain,         scatter tf32 to g_v
#define ASTR 36             // 36 % 32 == 4 -> conflict-free fragment loads
#define GA_ST (128*ASTR)    // u32 per matrix per stage (4608)
#define GEMM_STAGES 3
#define GEMM_SMEM (GEMM_STAGES*2*GA_ST*4)   // 110592 B

template<int MODE>
__global__ __launch_bounds__(256, 2) void gemm_tc(
    const float* __restrict__ bias, float* __restrict__ Cout)
{
    const unsigned* A  = (MODE == 0) ? g_att : (MODE == 1) ? g_qin
                        : (MODE == 2) ? g_kin : g_vin;
    const unsigned* Wt = (MODE == 0) ? g_wo  : (MODE == 1) ? g_wq
                        : (MODE == 2) ? g_wk : g_wv;
    extern __shared__ unsigned sm[];

    int tid  = threadIdx.x;
    int lane = tid & 31, wid = tid >> 5;
    int wm = wid & 1, wn = wid >> 1;
    int g = lane >> 2, tg = lane & 3;
    int m0 = blockIdx.y * 128;
    int n0 = blockIdx.x * 128;

    float c[4][4][4];
    #pragma unroll
    for (int mt = 0; mt < 4; mt++)
        #pragma unroll
        for (int nt = 0; nt < 4; nt++)
            #pragma unroll
            for (int j = 0; j < 4; j++) c[mt][nt][j] = 0.f;

    int rowi[4], kci[4];
    #pragma unroll
    for (int i = 0; i < 4; i++) {
        int f4 = tid + i*256;
        rowi[i] = f4 >> 3;          // 0..127
        kci[i]  = (f4 & 7) << 2;    // 0,4,..,28
    }

    const int T = NE / 32;          // 32 k-tiles

    auto issue = [&](int t) {
        unsigned* As = sm + (t % GEMM_STAGES) * 2 * GA_ST;
        unsigned* Bs = As + GA_ST;
        int kk = t * 32;
        #pragma unroll
        for (int i = 0; i < 4; i++) {
            cp16(&As[rowi[i]*ASTR + kci[i]], A  + (size_t)(m0+rowi[i])*NE + kk + kci[i]);
            cp16(&Bs[rowi[i]*ASTR + kci[i]], Wt + (size_t)(n0+rowi[i])*NE + kk + kci[i]);
        }
        CP_COMMIT();
    };

    issue(0); issue(1);

    for (int t = 0; t < T; t++) {
        if (t < T-1) asm volatile("cp.async.wait_group 1;" ::: "memory");
        else         asm volatile("cp.async.wait_group 0;" ::: "memory");
        __syncthreads();
        if (t + 2 < T) issue(t + 2);   // writes stage (t+2)%3 == (t-1)%3, protected by the sync above

        const unsigned* As = sm + (t % GEMM_STAGES) * 2 * GA_ST;
        const unsigned* Bs = As + GA_ST;
        #pragma unroll
        for (int ks = 0; ks < 4; ks++) {
            unsigned a[4][4], b[4][2];
            int cidx = ks*8 + tg;
            #pragma unroll
            for (int mt = 0; mt < 4; mt++) {
                int r = wm*64 + mt*16 + g;
                a[mt][0] = As[r*ASTR + cidx];
                a[mt][1] = As[(r+8)*ASTR + cidx];
                a[mt][2] = As[r*ASTR + cidx + 4];
                a[mt][3] = As[(r+8)*ASTR + cidx + 4];
            }
            #pragma unroll
            for (int nt = 0; nt < 4; nt++) {
                int n = wn*32 + nt*8 + g;
                b[nt][0] = Bs[n*ASTR + cidx];
                b[nt][1] = Bs[n*ASTR + cidx + 4];
            }
            #pragma unroll
            for (int mt = 0; mt < 4; mt++)
                #pragma unroll
                for (int nt = 0; nt < 4; nt++)
                    mma_tf32(c[mt][nt], a[mt], b[nt]);
        }
    }

    // Epilogue: per (mt,nt) tile the thread holds (r0,col),(r0,col+1),(r0+8,col),(r0+8,col+1)
    // with col even -> perfect RoPE even/odd pairing.
    #pragma unroll
    for (int mt = 0; mt < 4; mt++) {
        int r0 = m0 + wm*64 + mt*16 + g;
        #pragma unroll
        for (int nt = 0; nt < 4; nt++) {
            int col = n0 + wn*32 + nt*8 + 2*tg;
            float b0 = bias[col], b1 = bias[col+1];
            float v00 = c[mt][nt][0] + b0, v01 = c[mt][nt][1] + b1;  // row r0
            float v10 = c[mt][nt][2] + b0, v11 = c[mt][nt][3] + b1;  // row r0+8
            if (MODE == 0) {
                *(float2*)(Cout + (size_t)r0*NE + col)     = make_float2(v00, v01);
                *(float2*)(Cout + (size_t)(r0+8)*NE + col) = make_float2(v10, v11);
            } else {
                unsigned* dstbase = (MODE == 1) ? g_q : (MODE == 2) ? g_k : g_v;
                int h = col >> 6;
                int d = col & 63;               // even
                #pragma unroll
                for (int rr = 0; rr < 2; rr++) {
                    int r = r0 + rr*8;
                    int b = r >> 11;            // / NS
                    int s = r & (NS-1);
                    float ve = rr ? v10 : v00;
                    float vo = rr ? v11 : v01;
                    float oe, oo;
                    if (MODE == 3) {
                        oe = ve; oo = vo;
                    } else {
                        int ti = (d >> 1)*NS + s;
                        float cs = g_cos[ti];
                        float sn = g_sin[ti];
                        oe = ve*cs - vo*sn;
                        oo = vo*cs + ve*sn;
                        if (MODE == 1) { oe *= 0.125f; oo *= 0.125f; }
                    }
                    *(uint2*)(dstbase + ((size_t)((b*NH + h)*NS + s))*ND + d)
                        = make_uint2(f2tf(oe), f2tf(oo));
                }
            }
        }
    }
}

// ---------------- Flash attention, tf32 tensor cores, cp.async pipeline ------
// CTA: 128 q-rows, 8 warps (16 q-rows each). 64-key tiles, 3-stage pipeline.
#define KSTR 68   // 68 % 32 == 4 : conflict-free for (g, tg) pattern
#define VSTR 72   // 72 % 32 == 8 : conflict-free for (tg row, g col) pattern
#define KST (64*KSTR)
#define VST (64*VSTR)
#define ATTN_STAGES 3
#define ATTN_SMEM (ATTN_STAGES*(KST + VST)*4)   // 107520 B

__global__ __launch_bounds__(256, 2) void attn_tc()
{
    extern __shared__ unsigned sm[];

    int tid  = threadIdx.x;
    int lane = tid & 31, wid = tid >> 5;
    int g = lane >> 2, tg = lane & 3;
    int bh = blockIdx.y;
    int q0 = blockIdx.x * 128;

    const unsigned* qp = g_q + (size_t)bh * NS * ND;
    const unsigned* kp = g_k + (size_t)bh * NS * ND;
    const unsigned* vp = g_v + (size_t)bh * NS * ND;

    // Q fragments for this warp's 16 rows (rows r0, r0+8), all of d=64 (already tf32 bits)
    int r0 = q0 + wid*16 + g;
    unsigned qa[8][4];
    #pragma unroll
    for (int ks = 0; ks < 8; ks++) {
        int cc = ks*8 + tg;
        qa[ks][0] = qp[(size_t)r0*ND + cc];
        qa[ks][1] = qp[(size_t)(r0+8)*ND + cc];
        qa[ks][2] = qp[(size_t)r0*ND + cc + 4];
        qa[ks][3] = qp[(size_t)(r0+8)*ND + cc + 4];
    }

    float o[8][4];
    #pragma unroll
    for (int nt = 0; nt < 8; nt++)
        #pragma unroll
        for (int j = 0; j < 4; j++) o[nt][j] = 0.f;
    float m0r = -INFINITY, m1r = -INFINITY, l0 = 0.f, l1 = 0.f;

    int srcA = (lane & ~3) | (tg >> 1);
    int srcB = srcA + 2;
    bool oddl = (tg & 1);

    const int T = NS / 64;   // 32 key tiles

    auto issue = [&](int t) {
        unsigned* Ks = sm + (t % ATTN_STAGES) * (KST + VST);
        unsigned* Vs = Ks + KST;
        int kt = t * 64;
        #pragma unroll
        for (int i = 0; i < 4; i++) {
            int f4 = tid + i*256;
            int rr = f4 >> 4;            // 0..63
            int cc = (f4 & 15) << 2;     // 0..60
            cp16(&Ks[rr*KSTR + cc], kp + (size_t)(kt+rr)*ND + cc);
            cp16(&Vs[rr*VSTR + cc], vp + (size_t)(kt+rr)*ND + cc);
        }
        CP_COMMIT();
    };

    issue(0); issue(1);

    for (int t = 0; t < T; t++) {
        if (t < T-1) asm volatile("cp.async.wait_group 1;" ::: "memory");
        else         asm volatile("cp.async.wait_group 0;" ::: "memory");
        __syncthreads();
        if (t + 2 < T) issue(t + 2);

        const unsigned* Ks = sm + (t % ATTN_STAGES) * (KST + VST);
        const unsigned* Vs = Ks + KST;

        // ---- S = Q K^T (per warp: 16 q-rows x 64 keys) ----
        float s[8][4];
        #pragma unroll
        for (int nt = 0; nt < 8; nt++)
            #pragma unroll
            for (int j = 0; j < 4; j++) s[nt][j] = 0.f;
        #pragma unroll
        for (int ks = 0; ks < 8; ks++) {
            int cidx = ks*8 + tg;
            #pragma unroll
            for (int nt = 0; nt < 8; nt++) {
                unsigned b[2];
                b[0] = Ks[(nt*8+g)*KSTR + cidx];
                b[1] = Ks[(nt*8+g)*KSTR + cidx + 4];
                mma_tf32(s[nt], qa[ks], b);
            }
        }

        // ---- online softmax (rewrites s[] with tf32 P bits) ----
        float cm0 = -INFINITY, cm1 = -INFINITY;
        #pragma unroll
        for (int nt = 0; nt < 8; nt++) {
            cm0 = fmaxf(cm0, fmaxf(s[nt][0], s[nt][1]));
            cm1 = fmaxf(cm1, fmaxf(s[nt][2], s[nt][3]));
        }
        cm0 = fmaxf(cm0, __shfl_xor_sync(0xffffffffu, cm0, 1));
        cm0 = fmaxf(cm0, __shfl_xor_sync(0xffffffffu, cm0, 2));
        cm1 = fmaxf(cm1, __shfl_xor_sync(0xffffffffu, cm1, 1));
        cm1 = fmaxf(cm1, __shfl_xor_sync(0xffffffffu, cm1, 2));
        float mn0 = fmaxf(m0r, cm0), mn1 = fmaxf(m1r, cm1);
        float corr0 = __expf(m0r - mn0), corr1 = __expf(m1r - mn1);
        m0r = mn0; m1r = mn1;
        l0 *= corr0; l1 *= corr1;

        #pragma unroll
        for (int nt = 0; nt < 8; nt++) {
            float p0 = __expf(s[nt][0] - mn0);
            float p1 = __expf(s[nt][1] - mn0);
            float p2 = __expf(s[nt][2] - mn1);
            float p3 = __expf(s[nt][3] - mn1);
            l0 += p0 + p1;
            l1 += p2 + p3;
            o[nt][0] *= corr0; o[nt][1] *= corr0;
            o[nt][2] *= corr1; o[nt][3] *= corr1;
            s[nt][0] = __uint_as_float(f2tf(p0));
            s[nt][1] = __uint_as_float(f2tf(p1));
            s[nt][2] = __uint_as_float(f2tf(p2));
            s[nt][3] = __uint_as_float(f2tf(p3));
        }

        // ---- O += P V ----  (P C-frag -> A-frag via shuffles)
        #pragma unroll
        for (int ks = 0; ks < 8; ks++) {
            unsigned u0 = __float_as_uint(s[ks][0]);
            unsigned u1 = __float_as_uint(s[ks][1]);
            unsigned u2 = __float_as_uint(s[ks][2]);
            unsigned u3 = __float_as_uint(s[ks][3]);
            unsigned pa[4], e0, e1;
            e0 = __shfl_sync(0xffffffffu, u0, srcA);
            e1 = __shfl_sync(0xffffffffu, u1, srcA);
            pa[0] = oddl ? e1 : e0;
            e0 = __shfl_sync(0xffffffffu, u2, srcA);
            e1 = __shfl_sync(0xffffffffu, u3, srcA);
            pa[1] = oddl ? e1 : e0;
            e0 = __shfl_sync(0xffffffffu, u0, srcB);
            e1 = __shfl_sync(0xffffffffu, u1, srcB);
            pa[2] = oddl ? e1 : e0;
            e0 = __shfl_sync(0xffffffffu, u2, srcB);
            e1 = __shfl_sync(0xffffffffu, u3, srcB);
            pa[3] = oddl ? e1 : e0;
            #pragma unroll
            for (int nt = 0; nt < 8; nt++) {
                unsigned b[2];
                b[0] = Vs[(ks*8+tg)*VSTR + nt*8 + g];
                b[1] = Vs[(ks*8+tg+4)*VSTR + nt*8 + g];
                mma_tf32(o[nt], pa, b);
            }
        }
    }

    // ---- finalize: normalize and write tf32 bits to [B,S,H,D] ----
    l0 += __shfl_xor_sync(0xffffffffu, l0, 1);
    l0 += __shfl_xor_sync(0xffffffffu, l0, 2);
    l1 += __shfl_xor_sync(0xffffffffu, l1, 1);
    l1 += __shfl_xor_sync(0xffffffffu, l1, 2);
    float i0 = 1.0f / l0, i1 = 1.0f / l1;

    int b = bh >> 4, h = bh & 15;
    unsigned* dst0 = g_att + (((size_t)(b*NS + r0))  * NH + h) * ND;
    unsigned* dst1 = g_att + (((size_t)(b*NS + r0+8))* NH + h) * ND;
    #pragma unroll
    for (int nt = 0; nt < 8; nt++) {
        int col = nt*8 + 2*tg;
        *(uint2*)(dst0 + col) = make_uint2(f2tf(o[nt][0]*i0), f2tf(o[nt][1]*i0));
        *(uint2*)(dst1 + col) = make_uint2(f2tf(o[nt][2]*i1), f2tf(o[nt][3]*i1));
    }
}

// ------------------------------- launch --------------------------------------
extern "C" void kernel_launch(void* const* d_in, const int* in_sizes, int n_in,
                              void* d_out, int out_size)
{
    const float* query = (const float*)d_in[0];
    const float* key   = (const float*)d_in[1];
    const float* value = (const float*)d_in[2];
    const float* Wq    = (const float*)d_in[3];
    const float* bq    = (const float*)d_in[4];
    const float* Wk    = (const float*)d_in[5];
    const float* bk    = (const float*)d_in[6];
    const float* Wv    = (const float*)d_in[7];
    const float* bv    = (const float*)d_in[8];
    const float* Wo    = (const float*)d_in[9];
    const float* bo    = (const float*)d_in[10];
    float* out = (float*)d_out;

    cudaFuncSetAttribute(gemm_tc<0>, cudaFuncAttributeMaxDynamicSharedMemorySize, GEMM_SMEM);
    cudaFuncSetAttribute(gemm_tc<1>, cudaFuncAttributeMaxDynamicSharedMemorySize, GEMM_SMEM);
    cudaFuncSetAttribute(gemm_tc<2>, cudaFuncAttributeMaxDynamicSharedMemorySize, GEMM_SMEM);
    cudaFuncSetAttribute(gemm_tc<3>, cudaFuncAttributeMaxDynamicSharedMemorySize, GEMM_SMEM);
    cudaFuncSetAttribute(attn_tc,    cudaFuncAttributeMaxDynamicSharedMemorySize, ATTN_SMEM);

    const int n4_in = NM*NE/4;   // 1048576
    const int n4_w  = NE*NE/4;   // 262144

    init_tabs_kernel<<<(ND/2)*NS/256, 256>>>();
    cvt_kernel<<<n4_in/256, 256>>>((const float4*)query, n4_in, 0);
    cvt_kernel<<<n4_in/256, 256>>>((const float4*)key,   n4_in, 1);
    cvt_kernel<<<n4_in/256, 256>>>((const float4*)value, n4_in, 2);
    cvt_kernel<<<n4_w/256, 256>>>((const float4*)Wq, n4_w, 3);
    cvt_kernel<<<n4_w/256, 256>>>((const float4*)Wk, n4_w, 4);
    cvt_kernel<<<n4_w/256, 256>>>((const float4*)Wv, n4_w, 5);
    cvt_kernel<<<n4_w/256, 256>>>((const float4*)Wo, n4_w, 6);

    dim3 ggrid(NE/128, NM/128);   // (8, 32)
    gemm_tc<1><<<ggrid, 256, GEMM_SMEM>>>(bq, nullptr);
    gemm_tc<2><<<ggrid, 256, GEMM_SMEM>>>(bk, nullptr);
    gemm_tc<3><<<ggrid, 256, GEMM_SMEM>>>(bv, nullptr);
    attn_tc<<<dim3(NS/128, NB*NH), 256, ATTN_SMEM>>>();
    gemm_tc<0><<<ggrid, 256, GEMM_SMEM>>>(bo, out);
}

// round 6
// speedup vs baseline: 1.1190x; 1.0475x over previous
#include <cuda_runtime.h>
#include <math.h>

// Problem constants
#define NB 2
#define NS 2048
#define NE 1024
#define NH 16
#define ND 64
#define NM (NB*NS)   // 4096 rows

// Q scale: (1/sqrt(64)) * log2(e) so softmax can use ex2 directly
#define QSCALE 0.18033688011112042f

// ---------------- scratch (static device globals; no allocation) -------------
__device__ unsigned g_qin[NM*NE];     // tf32(query)
__device__ unsigned g_kin[NM*NE];     // tf32(key)
__device__ unsigned g_vin[NM*NE];     // tf32(value)
__device__ unsigned g_wq[NE*NE];      // tf32(Wq)
__device__ unsigned g_wk[NE*NE];
__device__ unsigned g_wv[NE*NE];
__device__ unsigned g_wo[NE*NE];
__device__ unsigned g_q[NB*NH*NS*ND]; // tf32(roped Q * 0.125*log2e), [B,H,S,D]
__device__ unsigned g_k[NB*NH*NS*ND]; // tf32(roped K)
__device__ unsigned g_v[NB*NH*NS*ND]; // tf32(V)
__device__ unsigned g_att[NM*NE];     // tf32(attention out), [B,S,H,D]
__device__ float g_cos[(ND/2)*NS];    // [d2][s]
__device__ float g_sin[(ND/2)*NS];

// ---------------- tf32 / math helpers ----------------------------------------
__device__ __forceinline__ unsigned f2tf(float x) {
    unsigned u;
    asm("cvt.rna.tf32.f32 %0, %1;" : "=r"(u) : "f"(x));
    return u;
}
__device__ __forceinline__ float ex2(float x) {
    float r;
    asm("ex2.approx.f32 %0, %1;" : "=f"(r) : "f"(x));
    return r;
}
__device__ __forceinline__ void mma_tf32(float c[4], const unsigned a[4], const unsigned b[2]) {
    asm volatile(
        "mma.sync.aligned.m16n8k8.row.col.f32.tf32.tf32.f32 "
        "{%0,%1,%2,%3}, {%4,%5,%6,%7}, {%8,%9}, {%0,%1,%2,%3};"
        : "+f"(c[0]), "+f"(c[1]), "+f"(c[2]), "+f"(c[3])
        : "r"(a[0]), "r"(a[1]), "r"(a[2]), "r"(a[3]),
          "r"(b[0]), "r"(b[1]));
}
__device__ __forceinline__ void cp16(unsigned* smem_dst, const unsigned* gmem_src) {
    unsigned saddr = (unsigned)__cvta_generic_to_shared(smem_dst);
    asm volatile("cp.async.cg.shared.global [%0], [%1], 16;"
                 :: "r"(saddr), "l"(gmem_src) : "memory");
}
#define CP_COMMIT() asm volatile("cp.async.commit_group;" ::: "memory")

// ---------------- init kernels ------------------------------------------------
__global__ void init_tabs_kernel() {
    int idx = blockIdx.x * 256 + threadIdx.x;     // 0 .. 32*2048-1
    int d2 = idx >> 11;
    int s  = idx & (NS-1);
    double ex = (double)(2*d2) / (double)ND;
    float invf = (float)exp2(-ex * 13.287712379549449);
    float ang = (float)s * invf;
    float sn, cs;
    sincosf(ang, &sn, &cs);
    g_cos[idx] = cs;
    g_sin[idx] = sn;
}

// One fused fp32->tf32 conversion over all 7 tensors.
// uint4 segments: 3 inputs of IN4, then 4 weights of W4.
#define IN4 (NM*NE/4)    // 1048576
#define W4  (NE*NE/4)    // 262144
__global__ void cvt_all_kernel(
    const float4* __restrict__ q, const float4* __restrict__ k,
    const float4* __restrict__ v, const float4* __restrict__ wq,
    const float4* __restrict__ wk, const float4* __restrict__ wv,
    const float4* __restrict__ wo)
{
    long i = (long)blockIdx.x * 256 + threadIdx.x;
    const float4* src;
    uint4* dst;
    long o = i;
    if (i < IN4)                { src = q;  dst = (uint4*)g_qin; }
    else if ((o -= IN4) < IN4)  { src = k;  dst = (uint4*)g_kin; }
    else if ((o -= IN4) < IN4)  { src = v;  dst = (uint4*)g_vin; }
    else if ((o -= IN4) < W4)   { src = wq; dst = (uint4*)g_wq; }
    else if ((o -= W4) < W4)    { src = wk; dst = (uint4*)g_wk; }
    else if ((o -= W4) < W4)    { src = wv; dst = (uint4*)g_wv; }
    else { o -= W4;               src = wo; dst = (uint4*)g_wo; }
    float4 x = src[o];
    dst[o] = make_uint4(f2tf(x.x), f2tf(x.y), f2tf(x.z), f2tf(x.w));
}
#define CVT_TOTAL4 (3*IN4 + 4*W4)

// ---------------- GEMM: C[m,n] = sum_k A[m,k]*Wt[n,k] + bias[n] --------------
// BM=128, BN=128, BK=32. 256 threads = 8 warps (2 m-warps x 4 n-warps).
// 3-stage cp.async pipeline, one __syncthreads per k-tile, 2 CTAs/SM.
#define ASTR 36
#define GA_ST (128*ASTR)
#define GEMM_STAGES 3
#define GEMM_SMEM (GEMM_STAGES*2*GA_ST*4)

template<int MODE>
__global__ __launch_bounds__(256, 2) void gemm_tc(
    const float* __restrict__ bias, float* __restrict__ Cout)
{
    const unsigned* A  = (MODE == 0) ? g_att : (MODE == 1) ? g_qin
                        : (MODE == 2) ? g_kin : g_vin;
    const unsigned* Wt = (MODE == 0) ? g_wo  : (MODE == 1) ? g_wq
                        : (MODE == 2) ? g_wk : g_wv;
    extern __shared__ unsigned sm[];

    int tid  = threadIdx.x;
    int lane = tid & 31, wid = tid >> 5;
    int wm = wid & 1, wn = wid >> 1;
    int g = lane >> 2, tg = lane & 3;
    int m0 = blockIdx.y * 128;
    int n0 = blockIdx.x * 128;

    float c[4][4][4];
    #pragma unroll
    for (int mt = 0; mt < 4; mt++)
        #pragma unroll
        for (int nt = 0; nt < 4; nt++)
            #pragma unroll
            for (int j = 0; j < 4; j++) c[mt][nt][j] = 0.f;

    int rowi[4], kci[4];
    #pragma unroll
    for (int i = 0; i < 4; i++) {
        int f4 = tid + i*256;
        rowi[i] = f4 >> 3;
        kci[i]  = (f4 & 7) << 2;
    }

    const int T = NE / 32;

    auto issue = [&](int t) {
        unsigned* As = sm + (t % GEMM_STAGES) * 2 * GA_ST;
        unsigned* Bs = As + GA_ST;
        int kk = t * 32;
        #pragma unroll
        for (int i = 0; i < 4; i++) {
            cp16(&As[rowi[i]*ASTR + kci[i]], A  + (size_t)(m0+rowi[i])*NE + kk + kci[i]);
            cp16(&Bs[rowi[i]*ASTR + kci[i]], Wt + (size_t)(n0+rowi[i])*NE + kk + kci[i]);
        }
        CP_COMMIT();
    };

    issue(0); issue(1);

    for (int t = 0; t < T; t++) {
        if (t < T-1) asm volatile("cp.async.wait_group 1;" ::: "memory");
        else         asm volatile("cp.async.wait_group 0;" ::: "memory");
        __syncthreads();
        if (t + 2 < T) issue(t + 2);

        const unsigned* As = sm + (t % GEMM_STAGES) * 2 * GA_ST;
        const unsigned* Bs = As + GA_ST;
        #pragma unroll
        for (int ks = 0; ks < 4; ks++) {
            unsigned a[4][4], b[4][2];
            int cidx = ks*8 + tg;
            #pragma unroll
            for (int mt = 0; mt < 4; mt++) {
                int r = wm*64 + mt*16 + g;
                a[mt][0] = As[r*ASTR + cidx];
                a[mt][1] = As[(r+8)*ASTR + cidx];
                a[mt][2] = As[r*ASTR + cidx + 4];
                a[mt][3] = As[(r+8)*ASTR + cidx + 4];
            }
            #pragma unroll
            for (int nt = 0; nt < 4; nt++) {
                int n = wn*32 + nt*8 + g;
                b[nt][0] = Bs[n*ASTR + cidx];
                b[nt][1] = Bs[n*ASTR + cidx + 4];
            }
            #pragma unroll
            for (int mt = 0; mt < 4; mt++)
                #pragma unroll
                for (int nt = 0; nt < 4; nt++)
                    mma_tf32(c[mt][nt], a[mt], b[nt]);
        }
    }

    #pragma unroll
    for (int mt = 0; mt < 4; mt++) {
        int r0 = m0 + wm*64 + mt*16 + g;
        #pragma unroll
        for (int nt = 0; nt < 4; nt++) {
            int col = n0 + wn*32 + nt*8 + 2*tg;
            float b0 = bias[col], b1 = bias[col+1];
            float v00 = c[mt][nt][0] + b0, v01 = c[mt][nt][1] + b1;
            float v10 = c[mt][nt][2] + b0, v11 = c[mt][nt][3] + b1;
            if (MODE == 0) {
                *(float2*)(Cout + (size_t)r0*NE + col)     = make_float2(v00, v01);
                *(float2*)(Cout + (size_t)(r0+8)*NE + col) = make_float2(v10, v11);
            } else {
                unsigned* dstbase = (MODE == 1) ? g_q : (MODE == 2) ? g_k : g_v;
                int h = col >> 6;
                int d = col & 63;
                #pragma unroll
                for (int rr = 0; rr < 2; rr++) {
                    int r = r0 + rr*8;
                    int b = r >> 11;
                    int s = r & (NS-1);
                    float ve = rr ? v10 : v00;
                    float vo = rr ? v11 : v01;
                    float oe, oo;
                    if (MODE == 3) {
                        oe = ve; oo = vo;
                    } else {
                        int ti = (d >> 1)*NS + s;
                        float cs = g_cos[ti];
                        float sn = g_sin[ti];
                        oe = ve*cs - vo*sn;
                        oo = vo*cs + ve*sn;
                        if (MODE == 1) { oe *= QSCALE; oo *= QSCALE; }
                    }
                    *(uint2*)(dstbase + ((size_t)((b*NH + h)*NS + s))*ND + d)
                        = make_uint2(f2tf(oe), f2tf(oo));
                }
            }
        }
    }
}

// ---------------- Flash attention, tf32, 32 q-rows per warp ------------------
// CTA: 128 q-rows, 4 warps (32 q-rows = 2 m16 blocks each). 64-key tiles,
// 3-stage cp.async pipeline, 2 CTAs/SM. K/V b-fragments are shared across the
// two m-blocks -> half the smem traffic per q-row vs 16q/warp.
#define KSTR 68
#define VSTR 72
#define KST (64*KSTR)
#define VST (64*VSTR)
#define ATTN_STAGES 3
#define ATTN_SMEM (ATTN_STAGES*(KST + VST)*4)

__global__ __launch_bounds__(128, 2) void attn_tc()
{
    extern __shared__ unsigned sm[];

    int tid  = threadIdx.x;
    int lane = tid & 31, wid = tid >> 5;       // 4 warps
    int g = lane >> 2, tg = lane & 3;
    int bh = blockIdx.y;
    int q0 = blockIdx.x * 128;

    const unsigned* qp = g_q + (size_t)bh * NS * ND;
    const unsigned* kp = g_k + (size_t)bh * NS * ND;
    const unsigned* vp = g_v + (size_t)bh * NS * ND;

    // Q fragments: 2 m-blocks of 16 rows each (rows rb+g, rb+g+8), tf32 bits
    int rbase = q0 + wid*32;
    unsigned qa[2][8][4];
    #pragma unroll
    for (int mt = 0; mt < 2; mt++) {
        int r0 = rbase + mt*16 + g;
        #pragma unroll
        for (int ks = 0; ks < 8; ks++) {
            int cc = ks*8 + tg;
            qa[mt][ks][0] = qp[(size_t)r0*ND + cc];
            qa[mt][ks][1] = qp[(size_t)(r0+8)*ND + cc];
            qa[mt][ks][2] = qp[(size_t)r0*ND + cc + 4];
            qa[mt][ks][3] = qp[(size_t)(r0+8)*ND + cc + 4];
        }
    }

    float o[2][8][4];
    #pragma unroll
    for (int mt = 0; mt < 2; mt++)
        #pragma unroll
        for (int nt = 0; nt < 8; nt++)
            #pragma unroll
            for (int j = 0; j < 4; j++) o[mt][nt][j] = 0.f;
    float mr[2][2], lr[2][2];
    #pragma unroll
    for (int mt = 0; mt < 2; mt++) {
        mr[mt][0] = -INFINITY; mr[mt][1] = -INFINITY;
        lr[mt][0] = 0.f;       lr[mt][1] = 0.f;
    }

    int srcA = (lane & ~3) | (tg >> 1);
    int srcB = srcA + 2;
    bool oddl = (tg & 1);

    const int T = NS / 64;

    auto issue = [&](int t) {
        unsigned* Ks = sm + (t % ATTN_STAGES) * (KST + VST);
        unsigned* Vs = Ks + KST;
        int kt = t * 64;
        #pragma unroll
        for (int i = 0; i < 8; i++) {
            int f4 = tid + i*128;        // 0..1023
            int rr = f4 >> 4;            // 0..63
            int cc = (f4 & 15) << 2;     // 0..60
            cp16(&Ks[rr*KSTR + cc], kp + (size_t)(kt+rr)*ND + cc);
            cp16(&Vs[rr*VSTR + cc], vp + (size_t)(kt+rr)*ND + cc);
        }
        CP_COMMIT();
    };

    issue(0); issue(1);

    for (int t = 0; t < T; t++) {
        if (t < T-1) asm volatile("cp.async.wait_group 1;" ::: "memory");
        else         asm volatile("cp.async.wait_group 0;" ::: "memory");
        __syncthreads();
        if (t + 2 < T) issue(t + 2);

        const unsigned* Ks = sm + (t % ATTN_STAGES) * (KST + VST);
        const unsigned* Vs = Ks + KST;

        // ---- S = Q K^T : 32 q-rows x 64 keys per warp ----
        float s[2][8][4];
        #pragma unroll
        for (int mt = 0; mt < 2; mt++)
            #pragma unroll
            for (int nt = 0; nt < 8; nt++)
                #pragma unroll
                for (int j = 0; j < 4; j++) s[mt][nt][j] = 0.f;
        #pragma unroll
        for (int ks = 0; ks < 8; ks++) {
            int cidx = ks*8 + tg;
            #pragma unroll
            for (int nt = 0; nt < 8; nt++) {
                unsigned b[2];
                b[0] = Ks[(nt*8+g)*KSTR + cidx];
                b[1] = Ks[(nt*8+g)*KSTR + cidx + 4];
                mma_tf32(s[0][nt], qa[0][ks], b);   // b shared across both m-blocks
                mma_tf32(s[1][nt], qa[1][ks], b);
            }
        }

        // ---- online softmax per m-block (scores already in log2 domain) ----
        float corr[2][2];
        #pragma unroll
        for (int mt = 0; mt < 2; mt++) {
            float cm0 = -INFINITY, cm1 = -INFINITY;
            #pragma unroll
            for (int nt = 0; nt < 8; nt++) {
                cm0 = fmaxf(cm0, fmaxf(s[mt][nt][0], s[mt][nt][1]));
                cm1 = fmaxf(cm1, fmaxf(s[mt][nt][2], s[mt][nt][3]));
            }
            cm0 = fmaxf(cm0, __shfl_xor_sync(0xffffffffu, cm0, 1));
            cm0 = fmaxf(cm0, __shfl_xor_sync(0xffffffffu, cm0, 2));
            cm1 = fmaxf(cm1, __shfl_xor_sync(0xffffffffu, cm1, 1));
            cm1 = fmaxf(cm1, __shfl_xor_sync(0xffffffffu, cm1, 2));
            float mn0 = fmaxf(mr[mt][0], cm0), mn1 = fmaxf(mr[mt][1], cm1);
            corr[mt][0] = ex2(mr[mt][0] - mn0);
            corr[mt][1] = ex2(mr[mt][1] - mn1);
            mr[mt][0] = mn0; mr[mt][1] = mn1;
            lr[mt][0] *= corr[mt][0];
            lr[mt][1] *= corr[mt][1];

            #pragma unroll
            for (int nt = 0; nt < 8; nt++) {
                float p0 = ex2(s[mt][nt][0] - mn0);
                float p1 = ex2(s[mt][nt][1] - mn0);
                float p2 = ex2(s[mt][nt][2] - mn1);
                float p3 = ex2(s[mt][nt][3] - mn1);
                lr[mt][0] += p0 + p1;
                lr[mt][1] += p2 + p3;
                o[mt][nt][0] *= corr[mt][0]; o[mt][nt][1] *= corr[mt][0];
                o[mt][nt][2] *= corr[mt][1]; o[mt][nt][3] *= corr[mt][1];
                s[mt][nt][0] = __uint_as_float(f2tf(p0));
                s[mt][nt][1] = __uint_as_float(f2tf(p1));
                s[mt][nt][2] = __uint_as_float(f2tf(p2));
                s[mt][nt][3] = __uint_as_float(f2tf(p3));
            }
        }

        // ---- O += P V ----  (P C-frag -> A-frag via shuffles; V b shared)
        #pragma unroll
        for (int ks = 0; ks < 8; ks++) {
            unsigned pa[2][4];
            #pragma unroll
            for (int mt = 0; mt < 2; mt++) {
                unsigned u0 = __float_as_uint(s[mt][ks][0]);
                unsigned u1 = __float_as_uint(s[mt][ks][1]);
                unsigned u2 = __float_as_uint(s[mt][ks][2]);
                unsigned u3 = __float_as_uint(s[mt][ks][3]);
                unsigned e0, e1;
                e0 = __shfl_sync(0xffffffffu, u0, srcA);
                e1 = __shfl_sync(0xffffffffu, u1, srcA);
                pa[mt][0] = oddl ? e1 : e0;
                e0 = __shfl_sync(0xffffffffu, u2, srcA);
                e1 = __shfl_sync(0xffffffffu, u3, srcA);
                pa[mt][1] = oddl ? e1 : e0;
                e0 = __shfl_sync(0xffffffffu, u0, srcB);
                e1 = __shfl_sync(0xffffffffu, u1, srcB);
                pa[mt][2] = oddl ? e1 : e0;
                e0 = __shfl_sync(0xffffffffu, u2, srcB);
                e1 = __shfl_sync(0xffffffffu, u3, srcB);
                pa[mt][3] = oddl ? e1 : e0;
            }
            #pragma unroll
            for (int nt = 0; nt < 8; nt++) {
                unsigned b[2];
                b[0] = Vs[(ks*8+tg)*VSTR + nt*8 + g];
                b[1] = Vs[(ks*8+tg+4)*VSTR + nt*8 + g];
                mma_tf32(o[0][nt], pa[0], b);
                mma_tf32(o[1][nt], pa[1], b);
            }
        }
    }

    // ---- finalize ----
    int b = bh >> 4, h = bh & 15;
    #pragma unroll
    for (int mt = 0; mt < 2; mt++) {
        float l0 = lr[mt][0], l1 = lr[mt][1];
        l0 += __shfl_xor_sync(0xffffffffu, l0, 1);
        l0 += __shfl_xor_sync(0xffffffffu, l0, 2);
        l1 += __shfl_xor_sync(0xffffffffu, l1, 1);
        l1 += __shfl_xor_sync(0xffffffffu, l1, 2);
        float i0 = 1.0f / l0, i1 = 1.0f / l1;
        int r0 = rbase + mt*16 + g;
        unsigned* dst0 = g_att + (((size_t)(b*NS + r0))  * NH + h) * ND;
        unsigned* dst1 = g_att + (((size_t)(b*NS + r0+8))* NH + h) * ND;
        #pragma unroll
        for (int nt = 0; nt < 8; nt++) {
            int col = nt*8 + 2*tg;
            *(uint2*)(dst0 + col) = make_uint2(f2tf(o[mt][nt][0]*i0), f2tf(o[mt][nt][1]*i0));
            *(uint2*)(dst1 + col) = make_uint2(f2tf(o[mt][nt][2]*i1), f2tf(o[mt][nt][3]*i1));
        }
    }
}

// ------------------------------- launch --------------------------------------
extern "C" void kernel_launch(void* const* d_in, const int* in_sizes, int n_in,
                              void* d_out, int out_size)
{
    const float* query = (const float*)d_in[0];
    const float* key   = (const float*)d_in[1];
    const float* value = (const float*)d_in[2];
    const float* Wq    = (const float*)d_in[3];
    const float* bq    = (const float*)d_in[4];
    const float* Wk    = (const float*)d_in[5];
    const float* bk    = (const float*)d_in[6];
    const float* Wv    = (const float*)d_in[7];
    const float* bv    = (const float*)d_in[8];
    const float* Wo    = (const float*)d_in[9];
    const float* bo    = (const float*)d_in[10];
    float* out = (float*)d_out;

    cudaFuncSetAttribute(gemm_tc<0>, cudaFuncAttributeMaxDynamicSharedMemorySize, GEMM_SMEM);
    cudaFuncSetAttribute(gemm_tc<1>, cudaFuncAttributeMaxDynamicSharedMemorySize, GEMM_SMEM);
    cudaFuncSetAttribute(gemm_tc<2>, cudaFuncAttributeMaxDynamicSharedMemorySize, GEMM_SMEM);
    cudaFuncSetAttribute(gemm_tc<3>, cudaFuncAttributeMaxDynamicSharedMemorySize, GEMM_SMEM);
    cudaFuncSetAttribute(attn_tc,    cudaFuncAttributeMaxDynamicSharedMemorySize, ATTN_SMEM);

    init_tabs_kernel<<<(ND/2)*NS/256, 256>>>();                       // launch 0
    cvt_all_kernel<<<CVT_TOTAL4/256, 256>>>(                          // launch 1
        (const float4*)query, (const float4*)key, (const float4*)value,
        (const float4*)Wq, (const float4*)Wk, (const float4*)Wv, (const float4*)Wo);

    dim3 ggrid(NE/128, NM/128);   // (8, 32)
    gemm_tc<1><<<ggrid, 256, GEMM_SMEM>>>(bq, nullptr);               // launch 2
    gemm_tc<2><<<ggrid, 256, GEMM_SMEM>>>(bk, nullptr);               // launch 3
    gemm_tc<3><<<ggrid, 256, GEMM_SMEM>>>(bv, nullptr);               // launch 4
    attn_tc<<<dim3(NS/128, NB*NH), 128, ATTN_SMEM>>>();               // launch 5 (profiled)
    gemm_tc<0><<<ggrid, 256, GEMM_SMEM>>>(bo, out);                   // launch 6
}

// round 7
// speedup vs baseline: 2.1297x; 1.9033x over previous
#include <cuda_runtime.h>
#include <cuda_fp16.h>
#include <math.h>

// Problem constants
#define NB 2
#define NS 2048
#define NE 1024
#define NH 16
#define ND 64
#define NM (NB*NS)   // 4096 rows

// Q scale: (1/sqrt(64)) * log2(e) so softmax can use ex2 directly
#define QSCALE 0.18033688011112042f

// ---------------- scratch (static device globals; no allocation) -------------
__device__ __half g_qin[NM*NE];     // fp16(query)
__device__ __half g_kin[NM*NE];
__device__ __half g_vin[NM*NE];
__device__ __half g_wq[NE*NE];
__device__ __half g_wk[NE*NE];
__device__ __half g_wv[NE*NE];
__device__ __half g_wo[NE*NE];
__device__ __half g_q[NB*NH*NS*ND]; // fp16(roped Q * QSCALE), [B,H,S,D]
__device__ __half g_k[NB*NH*NS*ND]; // fp16(roped K),          [B,H,S,D]
__device__ __half g_v[NB*NH*NS*ND]; // fp16(V),                [B,H,D,S]  (d-major!)
__device__ __half g_att[NM*NE];     // fp16(attn out), [B,S,H,D]
__device__ float g_cos[(ND/2)*NS];  // [d2][s]
__device__ float g_sin[(ND/2)*NS];

// ---------------- helpers ------------------------------------------------------
__device__ __forceinline__ unsigned pack_h2(float lo, float hi) {
    __half2 h = __floats2half2_rn(lo, hi);
    return *(unsigned*)&h;
}
__device__ __forceinline__ float ex2(float x) {
    float r;
    asm("ex2.approx.f32 %0, %1;" : "=f"(r) : "f"(x));
    return r;
}
__device__ __forceinline__ void mma_f16(float c[4], const unsigned a[4], const unsigned b[2]) {
    asm volatile(
        "mma.sync.aligned.m16n8k16.row.col.f32.f16.f16.f32 "
        "{%0,%1,%2,%3}, {%4,%5,%6,%7}, {%8,%9}, {%0,%1,%2,%3};"
        : "+f"(c[0]), "+f"(c[1]), "+f"(c[2]), "+f"(c[3])
        : "r"(a[0]), "r"(a[1]), "r"(a[2]), "r"(a[3]),
          "r"(b[0]), "r"(b[1]));
}
__device__ __forceinline__ void cp16(void* smem_dst, const void* gmem_src) {
    unsigned saddr = (unsigned)__cvta_generic_to_shared(smem_dst);
    asm volatile("cp.async.cg.shared.global [%0], [%1], 16;"
                 :: "r"(saddr), "l"(gmem_src) : "memory");
}
#define CP_COMMIT() asm volatile("cp.async.commit_group;" ::: "memory")

// ---------------- init kernels ------------------------------------------------
__global__ void init_tabs_kernel() {
    int idx = blockIdx.x * 256 + threadIdx.x;     // 0 .. 32*2048-1
    int d2 = idx >> 11;
    int s  = idx & (NS-1);
    double ex = (double)(2*d2) / (double)ND;
    float invf = (float)exp2(-ex * 13.287712379549449);
    float ang = (float)s * invf;
    float sn, cs;
    sincosf(ang, &sn, &cs);
    g_cos[idx] = cs;
    g_sin[idx] = sn;
}

// One fused fp32->fp16 conversion over all 7 tensors.
#define IN4 (NM*NE/4)    // 1048576 float4s
#define W4  (NE*NE/4)    // 262144
__global__ void cvt_all_kernel(
    const float4* __restrict__ q, const float4* __restrict__ k,
    const float4* __restrict__ v, const float4* __restrict__ wq,
    const float4* __restrict__ wk, const float4* __restrict__ wv,
    const float4* __restrict__ wo)
{
    long i = (long)blockIdx.x * 256 + threadIdx.x;
    const float4* src;
    uint2* dst;
    long o = i;
    if (i < IN4)                { src = q;  dst = (uint2*)g_qin; }
    else if ((o -= IN4) < IN4)  { src = k;  dst = (uint2*)g_kin; }
    else if ((o -= IN4) < IN4)  { src = v;  dst = (uint2*)g_vin; }
    else if ((o -= IN4) < W4)   { src = wq; dst = (uint2*)g_wq; }
    else if ((o -= W4) < W4)    { src = wk; dst = (uint2*)g_wk; }
    else if ((o -= W4) < W4)    { src = wv; dst = (uint2*)g_wv; }
    else { o -= W4;               src = wo; dst = (uint2*)g_wo; }
    float4 x = src[o];
    dst[o] = make_uint2(pack_h2(x.x, x.y), pack_h2(x.z, x.w));
}
#define CVT_TOTAL4 (3*IN4 + 4*W4)

// ---------------- GEMM: C[m,n] = sum_k A[m,k]*Wt[n,k] + bias[n] --------------
// fp16 mma m16n8k16. BM=BN=128, BK=64. 256 threads = 8 warps (2m x 4n),
// warp tile 64x32. 3-stage cp.async pipeline, 2 CTAs/SM.
// MODE 0: A=g_att, W=g_wo -> fp32 out. MODE 1: RoPE+QSCALE -> g_q [B,H,S,D].
// MODE 2: RoPE -> g_k. MODE 3: plain -> g_v [B,H,D,S] (d-major).
#define ASTR 72                       // halves; 144B row = 9x16B, %32 words = 4
#define GA_ST (128*ASTR)              // halves per matrix per stage
#define GEMM_STAGES 3
#define GEMM_SMEM (GEMM_STAGES*2*GA_ST*2)   // 110592 B

template<int MODE>
__global__ __launch_bounds__(256, 2) void gemm_tc(
    const float* __restrict__ bias, float* __restrict__ Cout)
{
    const __half* A  = (MODE == 0) ? g_att : (MODE == 1) ? g_qin
                      : (MODE == 2) ? g_kin : g_vin;
    const __half* Wt = (MODE == 0) ? g_wo  : (MODE == 1) ? g_wq
                      : (MODE == 2) ? g_wk : g_wv;
    extern __shared__ __half smh[];

    int tid  = threadIdx.x;
    int lane = tid & 31, wid = tid >> 5;
    int wm = wid & 1, wn = wid >> 1;
    int g = lane >> 2, tg = lane & 3;
    int m0 = blockIdx.y * 128;
    int n0 = blockIdx.x * 128;

    float c[4][4][4];
    #pragma unroll
    for (int mt = 0; mt < 4; mt++)
        #pragma unroll
        for (int nt = 0; nt < 4; nt++)
            #pragma unroll
            for (int j = 0; j < 4; j++) c[mt][nt][j] = 0.f;

    int rowi[4], kci[4];
    #pragma unroll
    for (int i = 0; i < 4; i++) {
        int f = tid + i*256;            // 0..1023 chunk id
        rowi[i] = f >> 3;               // 0..127
        kci[i]  = (f & 7) << 3;         // 0,8,..,56 halves
    }

    const int T = NE / 64;              // 16 k-tiles

    auto issue = [&](int t) {
        __half* As = smh + (t % GEMM_STAGES) * 2 * GA_ST;
        __half* Bs = As + GA_ST;
        int kk = t * 64;
        #pragma unroll
        for (int i = 0; i < 4; i++) {
            cp16(&As[rowi[i]*ASTR + kci[i]], A  + (size_t)(m0+rowi[i])*NE + kk + kci[i]);
            cp16(&Bs[rowi[i]*ASTR + kci[i]], Wt + (size_t)(n0+rowi[i])*NE + kk + kci[i]);
        }
        CP_COMMIT();
    };

    issue(0); issue(1);

    for (int t = 0; t < T; t++) {
        if (t < T-1) asm volatile("cp.async.wait_group 1;" ::: "memory");
        else         asm volatile("cp.async.wait_group 0;" ::: "memory");
        __syncthreads();
        if (t + 2 < T) issue(t + 2);

        const __half* As = smh + (t % GEMM_STAGES) * 2 * GA_ST;
        const __half* Bs = As + GA_ST;
        #pragma unroll
        for (int ks = 0; ks < 4; ks++) {         // 4 x k16
            int kc = ks*16 + 2*tg;
            unsigned a[4][4], b[4][2];
            #pragma unroll
            for (int mt = 0; mt < 4; mt++) {
                int r = wm*64 + mt*16 + g;
                a[mt][0] = *(const unsigned*)&As[r*ASTR + kc];
                a[mt][1] = *(const unsigned*)&As[(r+8)*ASTR + kc];
                a[mt][2] = *(const unsigned*)&As[r*ASTR + kc + 8];
                a[mt][3] = *(const unsigned*)&As[(r+8)*ASTR + kc + 8];
            }
            #pragma unroll
            for (int nt = 0; nt < 4; nt++) {
                int n = wn*32 + nt*8 + g;
                b[nt][0] = *(const unsigned*)&Bs[n*ASTR + kc];
                b[nt][1] = *(const unsigned*)&Bs[n*ASTR + kc + 8];
            }
            #pragma unroll
            for (int mt = 0; mt < 4; mt++)
                #pragma unroll
                for (int nt = 0; nt < 4; nt++)
                    mma_f16(c[mt][nt], a[mt], b[nt]);
        }
    }

    // Epilogue: thread holds (r0,col),(r0,col+1),(r0+8,col),(r0+8,col+1), col even.
    #pragma unroll
    for (int mt = 0; mt < 4; mt++) {
        int r0 = m0 + wm*64 + mt*16 + g;
        #pragma unroll
        for (int nt = 0; nt < 4; nt++) {
            int col = n0 + wn*32 + nt*8 + 2*tg;
            float b0 = bias[col], b1 = bias[col+1];
            float v00 = c[mt][nt][0] + b0, v01 = c[mt][nt][1] + b1;
            float v10 = c[mt][nt][2] + b0, v11 = c[mt][nt][3] + b1;
            if (MODE == 0) {
                *(float2*)(Cout + (size_t)r0*NE + col)     = make_float2(v00, v01);
                *(float2*)(Cout + (size_t)(r0+8)*NE + col) = make_float2(v10, v11);
            } else {
                int h = col >> 6;
                int d = col & 63;               // even
                #pragma unroll
                for (int rr = 0; rr < 2; rr++) {
                    int r = r0 + rr*8;
                    int b = r >> 11;
                    int s = r & (NS-1);
                    float ve = rr ? v10 : v00;
                    float vo = rr ? v11 : v01;
                    if (MODE == 3) {
                        // V d-major: [B,H,D,S]
                        size_t base = ((size_t)(b*NH + h)*ND + d)*NS + s;
                        g_v[base]      = __float2half_rn(ve);
                        g_v[base + NS] = __float2half_rn(vo);
                    } else {
                        int ti = (d >> 1)*NS + s;
                        float cs = g_cos[ti];
                        float sn = g_sin[ti];
                        float oe = ve*cs - vo*sn;
                        float oo = vo*cs + ve*sn;
                        if (MODE == 1) { oe *= QSCALE; oo *= QSCALE; }
                        __half* dstbase = (MODE == 1) ? g_q : g_k;
                        *(unsigned*)&dstbase[((size_t)((b*NH + h)*NS + s))*ND + d]
                            = pack_h2(oe, oo);
                    }
                }
            }
        }
    }
}

// ---------------- Flash attention, fp16 mma, 32 q-rows per warp --------------
// CTA: 128 q-rows, 4 warps. 64-key tiles, 3-stage cp.async, 2 CTAs/SM.
// K smem row-major [key][d]; V smem d-major [d][key] (loaded from d-major gmem).
// P C-fragments pack directly into PV A-fragments as half2 -> zero shuffles.
#define KSTR 72
#define KST (64*KSTR)     // halves per K (or V) tile
#define ATTN_STAGES 3
#define ATTN_SMEM (ATTN_STAGES*2*KST*2)   // 55296 B

__global__ __launch_bounds__(128, 2) void attn_tc()
{
    extern __shared__ __half smh[];

    int tid  = threadIdx.x;
    int lane = tid & 31, wid = tid >> 5;       // 4 warps
    int g = lane >> 2, tg = lane & 3;
    int bh = blockIdx.y;
    int q0 = blockIdx.x * 128;

    const __half* qp = g_q + (size_t)bh * NS * ND;
    const __half* kp = g_k + (size_t)bh * NS * ND;
    const __half* vp = g_v + (size_t)bh * ND * NS;   // d-major

    // Q fragments: 2 m-blocks x 4 ksteps(k16) x 4 regs (half2 each)
    int rbase = q0 + wid*32;
    unsigned qa[2][4][4];
    #pragma unroll
    for (int mt = 0; mt < 2; mt++) {
        int r0 = rbase + mt*16 + g;
        #pragma unroll
        for (int ks = 0; ks < 4; ks++) {
            int kc = ks*16 + 2*tg;
            qa[mt][ks][0] = *(const unsigned*)&qp[(size_t)r0*ND + kc];
            qa[mt][ks][1] = *(const unsigned*)&qp[(size_t)(r0+8)*ND + kc];
            qa[mt][ks][2] = *(const unsigned*)&qp[(size_t)r0*ND + kc + 8];
            qa[mt][ks][3] = *(const unsigned*)&qp[(size_t)(r0+8)*ND + kc + 8];
        }
    }

    float o[2][8][4];
    #pragma unroll
    for (int mt = 0; mt < 2; mt++)
        #pragma unroll
        for (int nt = 0; nt < 8; nt++)
            #pragma unroll
            for (int j = 0; j < 4; j++) o[mt][nt][j] = 0.f;
    float mr[2][2], lr[2][2];
    #pragma unroll
    for (int mt = 0; mt < 2; mt++) {
        mr[mt][0] = -INFINITY; mr[mt][1] = -INFINITY;
        lr[mt][0] = 0.f;       lr[mt][1] = 0.f;
    }

    const int T = NS / 64;

    auto issue = [&](int t) {
        __half* Ks = smh + (t % ATTN_STAGES) * 2 * KST;
        __half* Vs = Ks + KST;
        int kt = t * 64;
        #pragma unroll
        for (int i = 0; i < 4; i++) {
            int f = tid + i*128;         // 0..511 chunk id
            int rr = f >> 3;             // 0..63
            int cc = (f & 7) << 3;       // 0..56 halves
            cp16(&Ks[rr*KSTR + cc], kp + (size_t)(kt+rr)*ND + cc);        // K row-major
            cp16(&Vs[rr*KSTR + cc], vp + (size_t)rr*NS + kt + cc);        // V d-major
        }
        CP_COMMIT();
    };

    issue(0); issue(1);

    for (int t = 0; t < T; t++) {
        if (t < T-1) asm volatile("cp.async.wait_group 1;" ::: "memory");
        else         asm volatile("cp.async.wait_group 0;" ::: "memory");
        __syncthreads();
        if (t + 2 < T) issue(t + 2);

        const __half* Ks = smh + (t % ATTN_STAGES) * 2 * KST;
        const __half* Vs = Ks + KST;

        // ---- S = Q K^T : 32 q-rows x 64 keys per warp ----
        float s[2][8][4];
        #pragma unroll
        for (int mt = 0; mt < 2; mt++)
            #pragma unroll
            for (int nt = 0; nt < 8; nt++)
                #pragma unroll
                for (int j = 0; j < 4; j++) s[mt][nt][j] = 0.f;
        #pragma unroll
        for (int ks = 0; ks < 4; ks++) {
            int kc = ks*16 + 2*tg;
            #pragma unroll
            for (int nt = 0; nt < 8; nt++) {
                unsigned b[2];
                b[0] = *(const unsigned*)&Ks[(nt*8+g)*KSTR + kc];
                b[1] = *(const unsigned*)&Ks[(nt*8+g)*KSTR + kc + 8];
                mma_f16(s[0][nt], qa[0][ks], b);
                mma_f16(s[1][nt], qa[1][ks], b);
            }
        }

        // ---- online softmax (scores in log2 domain) ----
        unsigned up[2][8][2];
        #pragma unroll
        for (int mt = 0; mt < 2; mt++) {
            float cm0 = -INFINITY, cm1 = -INFINITY;
            #pragma unroll
            for (int nt = 0; nt < 8; nt++) {
                cm0 = fmaxf(cm0, fmaxf(s[mt][nt][0], s[mt][nt][1]));
                cm1 = fmaxf(cm1, fmaxf(s[mt][nt][2], s[mt][nt][3]));
            }
            cm0 = fmaxf(cm0, __shfl_xor_sync(0xffffffffu, cm0, 1));
            cm0 = fmaxf(cm0, __shfl_xor_sync(0xffffffffu, cm0, 2));
            cm1 = fmaxf(cm1, __shfl_xor_sync(0xffffffffu, cm1, 1));
            cm1 = fmaxf(cm1, __shfl_xor_sync(0xffffffffu, cm1, 2));
            float mn0 = fmaxf(mr[mt][0], cm0), mn1 = fmaxf(mr[mt][1], cm1);
            float corr0 = ex2(mr[mt][0] - mn0);
            float corr1 = ex2(mr[mt][1] - mn1);
            mr[mt][0] = mn0; mr[mt][1] = mn1;
            lr[mt][0] *= corr0;
            lr[mt][1] *= corr1;

            #pragma unroll
            for (int nt = 0; nt < 8; nt++) {
                float p0 = ex2(s[mt][nt][0] - mn0);
                float p1 = ex2(s[mt][nt][1] - mn0);
                float p2 = ex2(s[mt][nt][2] - mn1);
                float p3 = ex2(s[mt][nt][3] - mn1);
                lr[mt][0] += p0 + p1;
                lr[mt][1] += p2 + p3;
                o[mt][nt][0] *= corr0; o[mt][nt][1] *= corr0;
                o[mt][nt][2] *= corr1; o[mt][nt][3] *= corr1;
                up[mt][nt][0] = pack_h2(p0, p1);   // (row g,   cols 2tg,2tg+1)
                up[mt][nt][1] = pack_h2(p2, p3);   // (row g+8, cols 2tg,2tg+1)
            }
        }

        // ---- O += P V ----  (P C-frags ARE the k16 A-frags; V d-major B-frags)
        #pragma unroll
        for (int ks = 0; ks < 4; ks++) {          // keys 16ks..16ks+15
            unsigned pa[2][4];
            #pragma unroll
            for (int mt = 0; mt < 2; mt++) {
                pa[mt][0] = up[mt][2*ks][0];
                pa[mt][1] = up[mt][2*ks][1];
                pa[mt][2] = up[mt][2*ks+1][0];
                pa[mt][3] = up[mt][2*ks+1][1];
            }
            int kc = ks*16 + 2*tg;
            #pragma unroll
            for (int nt = 0; nt < 8; nt++) {
                unsigned b[2];
                b[0] = *(const unsigned*)&Vs[(nt*8+g)*KSTR + kc];
                b[1] = *(const unsigned*)&Vs[(nt*8+g)*KSTR + kc + 8];
                mma_f16(o[0][nt], pa[0], b);
                mma_f16(o[1][nt], pa[1], b);
            }
        }
    }

    // ---- finalize: normalize, write fp16 [B,S,H,D] ----
    int b = bh >> 4, h = bh & 15;
    #pragma unroll
    for (int mt = 0; mt < 2; mt++) {
        float l0 = lr[mt][0], l1 = lr[mt][1];
        l0 += __shfl_xor_sync(0xffffffffu, l0, 1);
        l0 += __shfl_xor_sync(0xffffffffu, l0, 2);
        l1 += __shfl_xor_sync(0xffffffffu, l1, 1);
        l1 += __shfl_xor_sync(0xffffffffu, l1, 2);
        float i0 = 1.0f / l0, i1 = 1.0f / l1;
        int r0 = rbase + mt*16 + g;
        __half* dst0 = g_att + (((size_t)(b*NS + r0))  * NH + h) * ND;
        __half* dst1 = g_att + (((size_t)(b*NS + r0+8))* NH + h) * ND;
        #pragma unroll
        for (int nt = 0; nt < 8; nt++) {
            int col = nt*8 + 2*tg;
            *(unsigned*)&dst0[col] = pack_h2(o[mt][nt][0]*i0, o[mt][nt][1]*i0);
            *(unsigned*)&dst1[col] = pack_h2(o[mt][nt][2]*i1, o[mt][nt][3]*i1);
        }
    }
}

// ------------------------------- launch --------------------------------------
extern "C" void kernel_launch(void* const* d_in, const int* in_sizes, int n_in,
                              void* d_out, int out_size)
{
    const float* query = (const float*)d_in[0];
    const float* key   = (const float*)d_in[1];
    const float* value = (const float*)d_in[2];
    const float* Wq    = (const float*)d_in[3];
    const float* bq    = (const float*)d_in[4];
    const float* Wk    = (const float*)d_in[5];
    const float* bk    = (const float*)d_in[6];
    const float* Wv    = (const float*)d_in[7];
    const float* bv    = (const float*)d_in[8];
    const float* Wo    = (const float*)d_in[9];
    const float* bo    = (const float*)d_in[10];
    float* out = (float*)d_out;

    cudaFuncSetAttribute(gemm_tc<0>, cudaFuncAttributeMaxDynamicSharedMemorySize, GEMM_SMEM);
    cudaFuncSetAttribute(gemm_tc<1>, cudaFuncAttributeMaxDynamicSharedMemorySize, GEMM_SMEM);
    cudaFuncSetAttribute(gemm_tc<2>, cudaFuncAttributeMaxDynamicSharedMemorySize, GEMM_SMEM);
    cudaFuncSetAttribute(gemm_tc<3>, cudaFuncAttributeMaxDynamicSharedMemorySize, GEMM_SMEM);
    cudaFuncSetAttribute(attn_tc,    cudaFuncAttributeMaxDynamicSharedMemorySize, ATTN_SMEM);

    init_tabs_kernel<<<(ND/2)*NS/256, 256>>>();                       // launch 0
    cvt_all_kernel<<<CVT_TOTAL4/256, 256>>>(                          // launch 1
        (const float4*)query, (const float4*)key, (const float4*)value,
        (const float4*)Wq, (const float4*)Wk, (const float4*)Wv, (const float4*)Wo);

    dim3 ggrid(NE/128, NM/128);   // (8, 32)
    gemm_tc<1><<<ggrid, 256, GEMM_SMEM>>>(bq, nullptr);               // launch 2
    gemm_tc<2><<<ggrid, 256, GEMM_SMEM>>>(bk, nullptr);               // launch 3
    gemm_tc<3><<<ggrid, 256, GEMM_SMEM>>>(bv, nullptr);               // launch 4
    attn_tc<<<dim3(NS/128, NB*NH), 128, ATTN_SMEM>>>();               // launch 5 (profiled)
    gemm_tc<0><<<ggrid, 256, GEMM_SMEM>>>(bo, out);                   // launch 6
}

// round 8
// speedup vs baseline: 2.3037x; 1.0817x over previous
#include <cuda_runtime.h>
#include <cuda_fp16.h>
#include <math.h>

// Problem constants
#define NB 2
#define NS 2048
#define NE 1024
#define NH 16
#define ND 64
#define NM (NB*NS)   // 4096 rows

// Q scale: (1/sqrt(64)) * log2(e) so softmax can use ex2 directly
#define QSCALE 0.18033688011112042f

// ---------------- scratch (static device globals; no allocation) -------------
__device__ __half g_qin[NM*NE];     // fp16(query)
__device__ __half g_kin[NM*NE];
__device__ __half g_vin[NM*NE];
__device__ __half g_wq[NE*NE];
__device__ __half g_wk[NE*NE];
__device__ __half g_wv[NE*NE];
__device__ __half g_wo[NE*NE];
__device__ __half g_q[NB*NH*NS*ND]; // fp16(roped Q * QSCALE), [B,H,S,D]
__device__ __half g_k[NB*NH*NS*ND]; // fp16(roped K),          [B,H,S,D]
__device__ __half g_v[NB*NH*NS*ND]; // fp16(V),                [B,H,D,S]  (d-major!)
__device__ __half g_att[NM*NE];     // fp16(attn out), [B,S,H,D]
__device__ float g_cos[(ND/2)*NS];  // [d2][s]
__device__ float g_sin[(ND/2)*NS];

// ---------------- helpers ------------------------------------------------------
__device__ __forceinline__ unsigned pack_h2(float lo, float hi) {
    __half2 h = __floats2half2_rn(lo, hi);
    return *(unsigned*)&h;
}
__device__ __forceinline__ float ex2(float x) {
    float r;
    asm("ex2.approx.f32 %0, %1;" : "=f"(r) : "f"(x));
    return r;
}
__device__ __forceinline__ void mma_f16(float c[4], const unsigned a[4], const unsigned b[2]) {
    asm volatile(
        "mma.sync.aligned.m16n8k16.row.col.f32.f16.f16.f32 "
        "{%0,%1,%2,%3}, {%4,%5,%6,%7}, {%8,%9}, {%0,%1,%2,%3};"
        : "+f"(c[0]), "+f"(c[1]), "+f"(c[2]), "+f"(c[3])
        : "r"(a[0]), "r"(a[1]), "r"(a[2]), "r"(a[3]),
          "r"(b[0]), "r"(b[1]));
}
__device__ __forceinline__ void ldsm4(unsigned r[4], const __half* p) {
    unsigned addr = (unsigned)__cvta_generic_to_shared(p);
    asm volatile("ldmatrix.sync.aligned.m8n8.x4.shared.b16 {%0,%1,%2,%3}, [%4];"
                 : "=r"(r[0]), "=r"(r[1]), "=r"(r[2]), "=r"(r[3]) : "r"(addr));
}
__device__ __forceinline__ void cp16(void* smem_dst, const void* gmem_src) {
    unsigned saddr = (unsigned)__cvta_generic_to_shared(smem_dst);
    asm volatile("cp.async.cg.shared.global [%0], [%1], 16;"
                 :: "r"(saddr), "l"(gmem_src) : "memory");
}
#define CP_COMMIT() asm volatile("cp.async.commit_group;" ::: "memory")

// ---------------- init kernels ------------------------------------------------
__global__ void init_tabs_kernel() {
    int idx = blockIdx.x * 256 + threadIdx.x;     // 0 .. 32*2048-1
    int d2 = idx >> 11;
    int s  = idx & (NS-1);
    double ex = (double)(2*d2) / (double)ND;
    float invf = (float)exp2(-ex * 13.287712379549449);
    float ang = (float)s * invf;
    float sn, cs;
    sincosf(ang, &sn, &cs);
    g_cos[idx] = cs;
    g_sin[idx] = sn;
}

// One fused fp32->fp16 conversion over all 7 tensors.
#define IN4 (NM*NE/4)    // 1048576 float4s
#define W4  (NE*NE/4)    // 262144
__global__ void cvt_all_kernel(
    const float4* __restrict__ q, const float4* __restrict__ k,
    const float4* __restrict__ v, const float4* __restrict__ wq,
    const float4* __restrict__ wk, const float4* __restrict__ wv,
    const float4* __restrict__ wo)
{
    long i = (long)blockIdx.x * 256 + threadIdx.x;
    const float4* src;
    uint2* dst;
    long o = i;
    if (i < IN4)                { src = q;  dst = (uint2*)g_qin; }
    else if ((o -= IN4) < IN4)  { src = k;  dst = (uint2*)g_kin; }
    else if ((o -= IN4) < IN4)  { src = v;  dst = (uint2*)g_vin; }
    else if ((o -= IN4) < W4)   { src = wq; dst = (uint2*)g_wq; }
    else if ((o -= W4) < W4)    { src = wk; dst = (uint2*)g_wk; }
    else if ((o -= W4) < W4)    { src = wv; dst = (uint2*)g_wv; }
    else { o -= W4;               src = wo; dst = (uint2*)g_wo; }
    float4 x = src[o];
    dst[o] = make_uint2(pack_h2(x.x, x.y), pack_h2(x.z, x.w));
}
#define CVT_TOTAL4 (3*IN4 + 4*W4)

// ---------------- GEMM: C[m,n] = sum_k A[m,k]*Wt[n,k] + bias[n] --------------
// fp16 mma m16n8k16 + ldmatrix fragment loads. BM=BN=128, BK=64.
// 256 threads = 8 warps (2m x 4n), warp tile 64x32. 3-stage cp.async, 2 CTAs/SM.
#define ASTR 72                       // halves; 144B row: rows step 4 banks -> LDSM conflict-free
#define GA_ST (128*ASTR)
#define GEMM_STAGES 3
#define GEMM_SMEM (GEMM_STAGES*2*GA_ST*2)   // 110592 B

template<int MODE>
__global__ __launch_bounds__(256, 2) void gemm_tc(
    const float* __restrict__ bias, float* __restrict__ Cout)
{
    const __half* A  = (MODE == 0) ? g_att : (MODE == 1) ? g_qin
                      : (MODE == 2) ? g_kin : g_vin;
    const __half* Wt = (MODE == 0) ? g_wo  : (MODE == 1) ? g_wq
                      : (MODE == 2) ? g_wk : g_wv;
    extern __shared__ __half smh[];

    int tid  = threadIdx.x;
    int lane = tid & 31, wid = tid >> 5;
    int wm = wid & 1, wn = wid >> 1;
    int g = lane >> 2, tg = lane & 3;
    int m0 = blockIdx.y * 128;
    int n0 = blockIdx.x * 128;

    // ldmatrix lane->row/col mapping
    int arow = ((lane >> 3) & 1)*8 + (lane & 7);   // A: g0/g2 row, g1/g3 row+8
    int acol = ((lane >> 4) & 1)*8;                //    g2/g3 col+8
    int brow = ((lane >> 4) & 1)*8 + (lane & 7);   // B: pairs of n8 tiles
    int bcol = ((lane >> 3) & 1)*8;

    float c[4][4][4];
    #pragma unroll
    for (int mt = 0; mt < 4; mt++)
        #pragma unroll
        for (int nt = 0; nt < 4; nt++)
            #pragma unroll
            for (int j = 0; j < 4; j++) c[mt][nt][j] = 0.f;

    int rowi[4], kci[4];
    #pragma unroll
    for (int i = 0; i < 4; i++) {
        int f = tid + i*256;
        rowi[i] = f >> 3;
        kci[i]  = (f & 7) << 3;
    }

    const int T = NE / 64;              // 16 k-tiles

    auto issue = [&](int t) {
        __half* As = smh + (t % GEMM_STAGES) * 2 * GA_ST;
        __half* Bs = As + GA_ST;
        int kk = t * 64;
        #pragma unroll
        for (int i = 0; i < 4; i++) {
            cp16(&As[rowi[i]*ASTR + kci[i]], A  + (size_t)(m0+rowi[i])*NE + kk + kci[i]);
            cp16(&Bs[rowi[i]*ASTR + kci[i]], Wt + (size_t)(n0+rowi[i])*NE + kk + kci[i]);
        }
        CP_COMMIT();
    };

    issue(0); issue(1);

    for (int t = 0; t < T; t++) {
        if (t < T-1) asm volatile("cp.async.wait_group 1;" ::: "memory");
        else         asm volatile("cp.async.wait_group 0;" ::: "memory");
        __syncthreads();
        if (t + 2 < T) issue(t + 2);

        const __half* As = smh + (t % GEMM_STAGES) * 2 * GA_ST;
        const __half* Bs = As + GA_ST;
        #pragma unroll
        for (int ks = 0; ks < 4; ks++) {         // 4 x k16
            int kc = ks*16;
            unsigned a[4][4], b[4][2];
            #pragma unroll
            for (int mt = 0; mt < 4; mt++)       // 4x ldmatrix.x4 (A 16x16 tiles)
                ldsm4(a[mt], &As[(wm*64 + mt*16 + arow)*ASTR + kc + acol]);
            #pragma unroll
            for (int np = 0; np < 2; np++) {     // 2x ldmatrix.x4 (B n8-pairs)
                unsigned tb[4];
                ldsm4(tb, &Bs[(wn*32 + np*16 + brow)*ASTR + kc + bcol]);
                b[2*np][0]   = tb[0]; b[2*np][1]   = tb[1];
                b[2*np+1][0] = tb[2]; b[2*np+1][1] = tb[3];
            }
            #pragma unroll
            for (int mt = 0; mt < 4; mt++)
                #pragma unroll
                for (int nt = 0; nt < 4; nt++)
                    mma_f16(c[mt][nt], a[mt], b[nt]);
        }
    }

    // Epilogue: thread holds (r0,col),(r0,col+1),(r0+8,col),(r0+8,col+1), col even.
    #pragma unroll
    for (int mt = 0; mt < 4; mt++) {
        int r0 = m0 + wm*64 + mt*16 + g;
        #pragma unroll
        for (int nt = 0; nt < 4; nt++) {
            int col = n0 + wn*32 + nt*8 + 2*tg;
            float b0 = bias[col], b1 = bias[col+1];
            float v00 = c[mt][nt][0] + b0, v01 = c[mt][nt][1] + b1;
            float v10 = c[mt][nt][2] + b0, v11 = c[mt][nt][3] + b1;
            if (MODE == 0) {
                *(float2*)(Cout + (size_t)r0*NE + col)     = make_float2(v00, v01);
                *(float2*)(Cout + (size_t)(r0+8)*NE + col) = make_float2(v10, v11);
            } else {
                int h = col >> 6;
                int d = col & 63;               // even
                #pragma unroll
                for (int rr = 0; rr < 2; rr++) {
                    int r = r0 + rr*8;
                    int b = r >> 11;
                    int s = r & (NS-1);
                    float ve = rr ? v10 : v00;
                    float vo = rr ? v11 : v01;
                    if (MODE == 3) {
                        // V d-major: [B,H,D,S]
                        size_t base = ((size_t)(b*NH + h)*ND + d)*NS + s;
                        g_v[base]      = __float2half_rn(ve);
                        g_v[base + NS] = __float2half_rn(vo);
                    } else {
                        int ti = (d >> 1)*NS + s;
                        float cs = g_cos[ti];
                        float sn = g_sin[ti];
                        float oe = ve*cs - vo*sn;
                        float oo = vo*cs + ve*sn;
                        if (MODE == 1) { oe *= QSCALE; oo *= QSCALE; }
                        __half* dstbase = (MODE == 1) ? g_q : g_k;
                        *(unsigned*)&dstbase[((size_t)((b*NH + h)*NS + s))*ND + d]
                            = pack_h2(oe, oo);
                    }
                }
            }
        }
    }
}

// ---------------- Flash attention, fp16 mma + ldmatrix -----------------------
// CTA: 128 q-rows, 4 warps. 64-key tiles, 3-stage cp.async, 2 CTAs/SM.
// K smem [key][d]; V smem [d][key] (from d-major gmem). P C-frags pack directly
// into PV A-frags (half2); K/V B-frags via ldmatrix.x4.
#define KSTR 72
#define KST (64*KSTR)     // halves per tile
#define ATTN_STAGES 3
#define ATTN_SMEM (ATTN_STAGES*2*KST*2)   // 55296 B

__global__ __launch_bounds__(128, 2) void attn_tc()
{
    extern __shared__ __half smh[];

    int tid  = threadIdx.x;
    int lane = tid & 31, wid = tid >> 5;       // 4 warps
    int g = lane >> 2, tg = lane & 3;
    int bh = blockIdx.y;
    int q0 = blockIdx.x * 128;

    int brow = ((lane >> 4) & 1)*8 + (lane & 7);
    int bcol = ((lane >> 3) & 1)*8;

    const __half* qp = g_q + (size_t)bh * NS * ND;
    const __half* kp = g_k + (size_t)bh * NS * ND;
    const __half* vp = g_v + (size_t)bh * ND * NS;   // d-major

    // Q fragments: 2 m-blocks x 4 ksteps(k16) x 4 regs (half2 each)
    int rbase = q0 + wid*32;
    unsigned qa[2][4][4];
    #pragma unroll
    for (int mt = 0; mt < 2; mt++) {
        int r0 = rbase + mt*16 + g;
        #pragma unroll
        for (int ks = 0; ks < 4; ks++) {
            int kc = ks*16 + 2*tg;
            qa[mt][ks][0] = *(const unsigned*)&qp[(size_t)r0*ND + kc];
            qa[mt][ks][1] = *(const unsigned*)&qp[(size_t)(r0+8)*ND + kc];
            qa[mt][ks][2] = *(const unsigned*)&qp[(size_t)r0*ND + kc + 8];
            qa[mt][ks][3] = *(const unsigned*)&qp[(size_t)(r0+8)*ND + kc + 8];
        }
    }

    float o[2][8][4];
    #pragma unroll
    for (int mt = 0; mt < 2; mt++)
        #pragma unroll
        for (int nt = 0; nt < 8; nt++)
            #pragma unroll
            for (int j = 0; j < 4; j++) o[mt][nt][j] = 0.f;
    float mr[2][2], lr[2][2];
    #pragma unroll
    for (int mt = 0; mt < 2; mt++) {
        mr[mt][0] = -INFINITY; mr[mt][1] = -INFINITY;
        lr[mt][0] = 0.f;       lr[mt][1] = 0.f;
    }

    const int T = NS / 64;

    auto issue = [&](int t) {
        __half* Ks = smh + (t % ATTN_STAGES) * 2 * KST;
        __half* Vs = Ks + KST;
        int kt = t * 64;
        #pragma unroll
        for (int i = 0; i < 4; i++) {
            int f = tid + i*128;
            int rr = f >> 3;
            int cc = (f & 7) << 3;
            cp16(&Ks[rr*KSTR + cc], kp + (size_t)(kt+rr)*ND + cc);   // K row-major
            cp16(&Vs[rr*KSTR + cc], vp + (size_t)rr*NS + kt + cc);   // V d-major
        }
        CP_COMMIT();
    };

    issue(0); issue(1);

    for (int t = 0; t < T; t++) {
        if (t < T-1) asm volatile("cp.async.wait_group 1;" ::: "memory");
        else         asm volatile("cp.async.wait_group 0;" ::: "memory");
        __syncthreads();
        if (t + 2 < T) issue(t + 2);

        const __half* Ks = smh + (t % ATTN_STAGES) * 2 * KST;
        const __half* Vs = Ks + KST;

        // ---- S = Q K^T : 32 q-rows x 64 keys per warp ----
        float s[2][8][4];
        #pragma unroll
        for (int mt = 0; mt < 2; mt++)
            #pragma unroll
            for (int nt = 0; nt < 8; nt++)
                #pragma unroll
                for (int j = 0; j < 4; j++) s[mt][nt][j] = 0.f;
        #pragma unroll
        for (int ks = 0; ks < 4; ks++) {
            int kc = ks*16;
            unsigned b[8][2];
            #pragma unroll
            for (int np = 0; np < 4; np++) {     // 4x ldmatrix.x4 -> 8 n8 b-frags
                unsigned tb[4];
                ldsm4(tb, &Ks[(np*16 + brow)*KSTR + kc + bcol]);
                b[2*np][0]   = tb[0]; b[2*np][1]   = tb[1];
                b[2*np+1][0] = tb[2]; b[2*np+1][1] = tb[3];
            }
            #pragma unroll
            for (int nt = 0; nt < 8; nt++) {
                mma_f16(s[0][nt], qa[0][ks], b[nt]);
                mma_f16(s[1][nt], qa[1][ks], b[nt]);
            }
        }

        // ---- online softmax (scores in log2 domain) ----
        unsigned up[2][8][2];
        #pragma unroll
        for (int mt = 0; mt < 2; mt++) {
            float cm0 = -INFINITY, cm1 = -INFINITY;
            #pragma unroll
            for (int nt = 0; nt < 8; nt++) {
                cm0 = fmaxf(cm0, fmaxf(s[mt][nt][0], s[mt][nt][1]));
                cm1 = fmaxf(cm1, fmaxf(s[mt][nt][2], s[mt][nt][3]));
            }
            cm0 = fmaxf(cm0, __shfl_xor_sync(0xffffffffu, cm0, 1));
            cm0 = fmaxf(cm0, __shfl_xor_sync(0xffffffffu, cm0, 2));
            cm1 = fmaxf(cm1, __shfl_xor_sync(0xffffffffu, cm1, 1));
            cm1 = fmaxf(cm1, __shfl_xor_sync(0xffffffffu, cm1, 2));
            float mn0 = fmaxf(mr[mt][0], cm0), mn1 = fmaxf(mr[mt][1], cm1);
            float corr0 = ex2(mr[mt][0] - mn0);
            float corr1 = ex2(mr[mt][1] - mn1);
            mr[mt][0] = mn0; mr[mt][1] = mn1;
            lr[mt][0] *= corr0;
            lr[mt][1] *= corr1;

            #pragma unroll
            for (int nt = 0; nt < 8; nt++) {
                float p0 = ex2(s[mt][nt][0] - mn0);
                float p1 = ex2(s[mt][nt][1] - mn0);
                float p2 = ex2(s[mt][nt][2] - mn1);
                float p3 = ex2(s[mt][nt][3] - mn1);
                lr[mt][0] += p0 + p1;
                lr[mt][1] += p2 + p3;
                o[mt][nt][0] *= corr0; o[mt][nt][1] *= corr0;
                o[mt][nt][2] *= corr1; o[mt][nt][3] *= corr1;
                up[mt][nt][0] = pack_h2(p0, p1);
                up[mt][nt][1] = pack_h2(p2, p3);
            }
        }

        // ---- O += P V ----  (P C-frags ARE the k16 A-frags; V B-frags via ldmatrix)
        #pragma unroll
        for (int ks = 0; ks < 4; ks++) {
            int kc = ks*16;
            unsigned pa[2][4];
            #pragma unroll
            for (int mt = 0; mt < 2; mt++) {
                pa[mt][0] = up[mt][2*ks][0];
                pa[mt][1] = up[mt][2*ks][1];
                pa[mt][2] = up[mt][2*ks+1][0];
                pa[mt][3] = up[mt][2*ks+1][1];
            }
            unsigned b[8][2];
            #pragma unroll
            for (int np = 0; np < 4; np++) {
                unsigned tb[4];
                ldsm4(tb, &Vs[(np*16 + brow)*KSTR + kc + bcol]);
                b[2*np][0]   = tb[0]; b[2*np][1]   = tb[1];
                b[2*np+1][0] = tb[2]; b[2*np+1][1] = tb[3];
            }
            #pragma unroll
            for (int nt = 0; nt < 8; nt++) {
                mma_f16(o[0][nt], pa[0], b[nt]);
                mma_f16(o[1][nt], pa[1], b[nt]);
            }
        }
    }

    // ---- finalize: normalize, write fp16 [B,S,H,D] ----
    int b = bh >> 4, h = bh & 15;
    #pragma unroll
    for (int mt = 0; mt < 2; mt++) {
        float l0 = lr[mt][0], l1 = lr[mt][1];
        l0 += __shfl_xor_sync(0xffffffffu, l0, 1);
        l0 += __shfl_xor_sync(0xffffffffu, l0, 2);
        l1 += __shfl_xor_sync(0xffffffffu, l1, 1);
        l1 += __shfl_xor_sync(0xffffffffu, l1, 2);
        float i0 = 1.0f / l0, i1 = 1.0f / l1;
        int r0 = rbase + mt*16 + g;
        __half* dst0 = g_att + (((size_t)(b*NS + r0))  * NH + h) * ND;
        __half* dst1 = g_att + (((size_t)(b*NS + r0+8))* NH + h) * ND;
        #pragma unroll
        for (int nt = 0; nt < 8; nt++) {
            int col = nt*8 + 2*tg;
            *(unsigned*)&dst0[col] = pack_h2(o[mt][nt][0]*i0, o[mt][nt][1]*i0);
            *(unsigned*)&dst1[col] = pack_h2(o[mt][nt][2]*i1, o[mt][nt][3]*i1);
        }
    }
}

// ------------------------------- launch --------------------------------------
extern "C" void kernel_launch(void* const* d_in, const int* in_sizes, int n_in,
                              void* d_out, int out_size)
{
    const float* query = (const float*)d_in[0];
    const float* key   = (const float*)d_in[1];
    const float* value = (const float*)d_in[2];
    const float* Wq    = (const float*)d_in[3];
    const float* bq    = (const float*)d_in[4];
    const float* Wk    = (const float*)d_in[5];
    const float* bk    = (const float*)d_in[6];
    const float* Wv    = (const float*)d_in[7];
    const float* bv    = (const float*)d_in[8];
    const float* Wo    = (const float*)d_in[9];
    const float* bo    = (const float*)d_in[10];
    float* out = (float*)d_out;

    cudaFuncSetAttribute(gemm_tc<0>, cudaFuncAttributeMaxDynamicSharedMemorySize, GEMM_SMEM);
    cudaFuncSetAttribute(gemm_tc<1>, cudaFuncAttributeMaxDynamicSharedMemorySize, GEMM_SMEM);
    cudaFuncSetAttribute(gemm_tc<2>, cudaFuncAttributeMaxDynamicSharedMemorySize, GEMM_SMEM);
    cudaFuncSetAttribute(gemm_tc<3>, cudaFuncAttributeMaxDynamicSharedMemorySize, GEMM_SMEM);
    cudaFuncSetAttribute(attn_tc,    cudaFuncAttributeMaxDynamicSharedMemorySize, ATTN_SMEM);

    init_tabs_kernel<<<(ND/2)*NS/256, 256>>>();                       // launch 0
    cvt_all_kernel<<<CVT_TOTAL4/256, 256>>>(                          // launch 1
        (const float4*)query, (const float4*)key, (const float4*)value,
        (const float4*)Wq, (const float4*)Wk, (const float4*)Wv, (const float4*)Wo);

    dim3 ggrid(NE/128, NM/128);   // (8, 32)
    gemm_tc<1><<<ggrid, 256, GEMM_SMEM>>>(bq, nullptr);               // launch 2
    gemm_tc<2><<<ggrid, 256, GEMM_SMEM>>>(bk, nullptr);               // launch 3
    gemm_tc<3><<<ggrid, 256, GEMM_SMEM>>>(bv, nullptr);               // launch 4
    attn_tc<<<dim3(NS/128, NB*NH), 128, ATTN_SMEM>>>();               // launch 5 (profiled)
    gemm_tc<0><<<ggrid, 256, GEMM_SMEM>>>(bo, out);                   // launch 6
}